// round 2
// baseline (speedup 1.0000x reference)
#include <cuda_runtime.h>
#include <cuda_bf16.h>
#include <cstddef>

// ---------------------------------------------------------------------------
// DCN forward: encoder MLP -> decoder MLP -> cdist argmin one-hot labels.
// Round 0: fp32 SIMT tiled GEMM baseline (128x128x16 tiles, 8x8/thread).
// ---------------------------------------------------------------------------

#define B_ROWS   8192
#define D_IN     1024
#define D_EMB    256
#define K_CENT   1024

// Ping-pong scratch (max intermediate: 8192 x 2048 floats = 64 MB each)
__device__ float g_buf0[(size_t)B_ROWS * 2048];
__device__ float g_buf1[(size_t)B_ROWS * 2048];
__device__ float g_c2[K_CENT];

// ---------------------------------------------------------------------------
// GEMM: C[M,N] = op( A[M,Kd] @ B + bias ), B either [Kd,N] (BTRANS=false)
// or [N,Kd] (BTRANS=true, used for emb @ centers^T).
// BM=BN=128, BK=16, 256 threads, 8x8 accumulators per thread.
// Requires: M%128==0, N%128==0, Kd%16==0 (all shapes here satisfy this).
// ---------------------------------------------------------------------------
template<bool RELU, bool BTRANS, bool HASBIAS>
__global__ __launch_bounds__(256)
void gemm_kernel(const float* __restrict__ A, const float* __restrict__ Bm,
                 const float* __restrict__ bias, float* __restrict__ C,
                 int M, int N, int Kd)
{
    constexpr int BK = 16;
    __shared__ float As[BK][132];   // padded to break store bank conflicts
    __shared__ float Bs[BK][128];

    const int tid = threadIdx.x;
    const int tx  = tid & 15;       // 0..15  (N direction)
    const int ty  = tid >> 4;       // 0..15  (M direction)
    const int brow = blockIdx.y * 128;
    const int bcol = blockIdx.x * 128;

    float acc[8][8];
    #pragma unroll
    for (int i = 0; i < 8; i++)
        #pragma unroll
        for (int j = 0; j < 8; j++) acc[i][j] = 0.0f;

    for (int kt = 0; kt < Kd; kt += BK) {
        // ---- load A tile (128 x 16), store transposed into As ----
        #pragma unroll
        for (int it = 0; it < 2; it++) {
            int t4  = tid + it * 256;          // 0..511 float4 slots
            int row = t4 >> 2;                 // 0..127
            int c4  = (t4 & 3) << 2;           // 0,4,8,12
            float4 v = *reinterpret_cast<const float4*>(
                A + (size_t)(brow + row) * Kd + kt + c4);
            As[c4 + 0][row] = v.x;
            As[c4 + 1][row] = v.y;
            As[c4 + 2][row] = v.z;
            As[c4 + 3][row] = v.w;
        }
        // ---- load B tile (16 x 128) ----
        if (!BTRANS) {
            #pragma unroll
            for (int it = 0; it < 2; it++) {
                int t4  = tid + it * 256;
                int row = t4 >> 5;             // 0..15
                int c4  = (t4 & 31) << 2;      // 0..124
                float4 v = *reinterpret_cast<const float4*>(
                    Bm + (size_t)(kt + row) * N + bcol + c4);
                *reinterpret_cast<float4*>(&Bs[row][c4]) = v;
            }
        } else {
            // Bm is [N, Kd]; tile covers n in [bcol, bcol+128), d in [kt, kt+16)
            #pragma unroll
            for (int it = 0; it < 2; it++) {
                int t4 = tid + it * 256;
                int n  = t4 >> 2;              // 0..127
                int d4 = (t4 & 3) << 2;        // 0,4,8,12
                float4 v = *reinterpret_cast<const float4*>(
                    Bm + (size_t)(bcol + n) * Kd + kt + d4);
                Bs[d4 + 0][n] = v.x;
                Bs[d4 + 1][n] = v.y;
                Bs[d4 + 2][n] = v.z;
                Bs[d4 + 3][n] = v.w;
            }
        }
        __syncthreads();

        #pragma unroll
        for (int k = 0; k < BK; k++) {
            float a[8], b[8];
            #pragma unroll
            for (int i = 0; i < 8; i++) a[i] = As[k][ty * 8 + i];
            #pragma unroll
            for (int j = 0; j < 8; j++) b[j] = Bs[k][tx * 8 + j];
            #pragma unroll
            for (int i = 0; i < 8; i++)
                #pragma unroll
                for (int j = 0; j < 8; j++)
                    acc[i][j] = fmaf(a[i], b[j], acc[i][j]);
        }
        __syncthreads();
    }

    // ---- epilogue: bias + relu + store (float4) ----
    #pragma unroll
    for (int i = 0; i < 8; i++) {
        int row = brow + ty * 8 + i;
        #pragma unroll
        for (int j = 0; j < 8; j += 4) {
            int col = bcol + tx * 8 + j;
            float4 v;
            v.x = acc[i][j + 0];
            v.y = acc[i][j + 1];
            v.z = acc[i][j + 2];
            v.w = acc[i][j + 3];
            if (HASBIAS) {
                v.x += bias[col + 0];
                v.y += bias[col + 1];
                v.z += bias[col + 2];
                v.w += bias[col + 3];
            }
            if (RELU) {
                v.x = fmaxf(v.x, 0.0f);
                v.y = fmaxf(v.y, 0.0f);
                v.z = fmaxf(v.z, 0.0f);
                v.w = fmaxf(v.w, 0.0f);
            }
            *reinterpret_cast<float4*>(C + (size_t)row * N + col) = v;
        }
    }
}

// ---------------------------------------------------------------------------
// c2[k] = sum_d centers[k][d]^2   (one warp per center row)
// ---------------------------------------------------------------------------
__global__ void c2_kernel(const float* __restrict__ centers, float* __restrict__ c2)
{
    int k    = blockIdx.x * 8 + (threadIdx.x >> 5);
    int lane = threadIdx.x & 31;
    float s = 0.0f;
    #pragma unroll
    for (int d = lane; d < D_EMB; d += 32) {
        float v = centers[(size_t)k * D_EMB + d];
        s = fmaf(v, v, s);
    }
    #pragma unroll
    for (int o = 16; o; o >>= 1) s += __shfl_xor_sync(0xFFFFFFFFu, s, o);
    if (lane == 0) c2[k] = s;
}

// ---------------------------------------------------------------------------
// Per-row argmin of max(e2 + c2 - 2*S, 0) with first-occurrence tie-break,
// then one-hot label write (as floats 0.0/1.0).
// One block (256 threads) per batch row.
// ---------------------------------------------------------------------------
__global__ void argmin_labels_kernel(const float* __restrict__ emb,
                                     const float* __restrict__ S,
                                     const float* __restrict__ c2,
                                     float* __restrict__ labels)
{
    const int row = blockIdx.x;
    const int tid = threadIdx.x;

    __shared__ float red[256];
    float v = emb[(size_t)row * D_EMB + tid];
    red[tid] = v * v;
    __syncthreads();
    #pragma unroll
    for (int s = 128; s > 0; s >>= 1) {
        if (tid < s) red[tid] += red[tid + s];
        __syncthreads();
    }
    const float e2 = red[0];
    __syncthreads();

    float best = 3.402823466e38f;
    int   bi   = 0;
    #pragma unroll
    for (int k = tid; k < K_CENT; k += 256) {
        float d = fmaxf(e2 + c2[k] - 2.0f * S[(size_t)row * K_CENT + k], 0.0f);
        if (d < best) { best = d; bi = k; }   // strict < keeps lowest index
    }

    __shared__ float sv[256];
    __shared__ int   si[256];
    sv[tid] = best;
    si[tid] = bi;
    __syncthreads();
    #pragma unroll
    for (int s = 128; s > 0; s >>= 1) {
        if (tid < s) {
            float v2 = sv[tid + s];
            int   i2 = si[tid + s];
            if (v2 < sv[tid] || (v2 == sv[tid] && i2 < si[tid])) {
                sv[tid] = v2;
                si[tid] = i2;
            }
        }
        __syncthreads();
    }
    const int win = si[0];

    #pragma unroll
    for (int k = tid; k < K_CENT; k += 256)
        labels[(size_t)row * K_CENT + k] = (k == win) ? 1.0f : 0.0f;
}

// ---------------------------------------------------------------------------
// Launch: 8 GEMMs + c2 + cdist GEMM + argmin/labels.
// ---------------------------------------------------------------------------
static inline void launch_gemm_rb(const float* A, const float* Bm, const float* bias,
                                  float* C, int M, int N, int Kd)
{   // relu + bias
    dim3 grid(N / 128, M / 128);
    gemm_kernel<true, false, true><<<grid, 256>>>(A, Bm, bias, C, M, N, Kd);
}
static inline void launch_gemm_b(const float* A, const float* Bm, const float* bias,
                                 float* C, int M, int N, int Kd)
{   // bias only (final layers)
    dim3 grid(N / 128, M / 128);
    gemm_kernel<false, false, true><<<grid, 256>>>(A, Bm, bias, C, M, N, Kd);
}

extern "C" void kernel_launch(void* const* d_in, const int* in_sizes, int n_in,
                              void* d_out, int out_size)
{
    (void)in_sizes; (void)n_in; (void)out_size;

    const float* x       = (const float*)d_in[0];
    const float* We[4]   = {(const float*)d_in[1], (const float*)d_in[3],
                            (const float*)d_in[5], (const float*)d_in[7]};
    const float* be[4]   = {(const float*)d_in[2], (const float*)d_in[4],
                            (const float*)d_in[6], (const float*)d_in[8]};
    const float* Wd[4]   = {(const float*)d_in[9],  (const float*)d_in[11],
                            (const float*)d_in[13], (const float*)d_in[15]};
    const float* bd[4]   = {(const float*)d_in[10], (const float*)d_in[12],
                            (const float*)d_in[14], (const float*)d_in[16]};
    const float* centers = (const float*)d_in[17];

    float* out    = (float*)d_out;
    float* recon  = out;                                    // [8192,1024]
    float* emb    = out + (size_t)B_ROWS * D_IN;             // [8192,256]
    float* labels = emb + (size_t)B_ROWS * D_EMB;            // [8192,1024]

    float *buf0, *buf1, *c2;
    cudaGetSymbolAddress((void**)&buf0, g_buf0);
    cudaGetSymbolAddress((void**)&buf1, g_buf1);
    cudaGetSymbolAddress((void**)&c2,  g_c2);

    // Encoder: 1024 -> 2048 -> 1024 -> 512 -> 256
    launch_gemm_rb(x,    We[0], be[0], buf0, B_ROWS, 2048, 1024);
    launch_gemm_rb(buf0, We[1], be[1], buf1, B_ROWS, 1024, 2048);
    launch_gemm_rb(buf1, We[2], be[2], buf0, B_ROWS, 512,  1024);
    launch_gemm_b (buf0, We[3], be[3], emb,  B_ROWS, 256,  512);

    // Decoder: 256 -> 512 -> 1024 -> 2048 -> 1024
    launch_gemm_rb(emb,  Wd[0], bd[0], buf1, B_ROWS, 512,  256);
    launch_gemm_rb(buf1, Wd[1], bd[1], buf0, B_ROWS, 1024, 512);
    launch_gemm_rb(buf0, Wd[2], bd[2], buf1, B_ROWS, 2048, 1024);
    launch_gemm_b (buf1, Wd[3], bd[3], recon, B_ROWS, 1024, 2048);

    // Clustering: c2, S = emb @ centers^T, argmin + one-hot
    c2_kernel<<<K_CENT / 8, 256>>>(centers, c2);
    {
        dim3 grid(K_CENT / 128, B_ROWS / 128);
        gemm_kernel<false, true, false><<<grid, 256>>>(emb, centers, nullptr,
                                                       buf0, B_ROWS, K_CENT, D_EMB);
    }
    argmin_labels_kernel<<<B_ROWS, 256>>>(emb, buf0, c2, labels);
}

// round 5
// speedup vs baseline: 1.9299x; 1.9299x over previous
#include <cuda_runtime.h>
#include <cuda_bf16.h>
#include <cstdint>
#include <cstddef>

#define B_ROWS 8192
#define D_IN   1024
#define D_EMB  256
#define K_CENT 1024
#define WSUM   4849664

// ---------------- device scratch ----------------
__device__ __align__(16) float g_xh[(size_t)B_ROWS * D_IN];
__device__ __align__(16) float g_xl[(size_t)B_ROWS * D_IN];
__device__ __align__(16) float g_h0h[(size_t)B_ROWS * 2048];
__device__ __align__(16) float g_h0l[(size_t)B_ROWS * 2048];
__device__ __align__(16) float g_h1h[(size_t)B_ROWS * 2048];
__device__ __align__(16) float g_h1l[(size_t)B_ROWS * 2048];
__device__ __align__(16) float g_eh[(size_t)B_ROWS * D_EMB];
__device__ __align__(16) float g_el[(size_t)B_ROWS * D_EMB];
__device__ __align__(16) __nv_bfloat16 g_ebh[(size_t)B_ROWS * D_EMB];
__device__ __align__(16) __nv_bfloat16 g_ebl[(size_t)B_ROWS * D_EMB];
__device__ __align__(16) float g_wh[WSUM];
__device__ __align__(16) float g_wl[WSUM];
__device__ __align__(16) __nv_bfloat16 g_wbh[WSUM];
__device__ __align__(16) __nv_bfloat16 g_wbl[WSUM];
__device__ __align__(16) float g_ch[K_CENT * D_EMB];
__device__ __align__(16) float g_cl[K_CENT * D_EMB];
__device__ __align__(16) __nv_bfloat16 g_d0h[(size_t)B_ROWS * 2048];
__device__ __align__(16) __nv_bfloat16 g_d0l[(size_t)B_ROWS * 2048];
__device__ __align__(16) __nv_bfloat16 g_d1h[(size_t)B_ROWS * 2048];
__device__ __align__(16) __nv_bfloat16 g_d1l[(size_t)B_ROWS * 2048];
__device__ float g_c2[K_CENT];

// ---------------- helpers ----------------
__device__ __forceinline__ uint32_t smem_u32(const void* p) {
    uint32_t a;
    asm("{ .reg .u64 t; cvta.to.shared.u64 t, %1; cvt.u32.u64 %0, t; }" : "=r"(a) : "l"(p));
    return a;
}
__device__ __forceinline__ void split_tf32(float v, float& h, float& l) {
    uint32_t u;
    asm("cvt.rna.tf32.f32 %0, %1;" : "=r"(u) : "f"(v));
    h = __uint_as_float(u);
    float r = v - h;
    asm("cvt.rna.tf32.f32 %0, %1;" : "=r"(u) : "f"(r));
    l = __uint_as_float(u);
}
__device__ __forceinline__ void split_bf16(float v, __nv_bfloat16& h, __nv_bfloat16& l) {
    h = __float2bfloat16(v);
    l = __float2bfloat16(v - __bfloat162float(h));
}
__device__ __forceinline__ void mma_tf32(float* d, const float* a, const float* b) {
    asm volatile(
        "mma.sync.aligned.m16n8k8.row.col.f32.tf32.tf32.f32 "
        "{%0,%1,%2,%3}, {%4,%5,%6,%7}, {%8,%9}, {%0,%1,%2,%3};"
        : "+f"(d[0]), "+f"(d[1]), "+f"(d[2]), "+f"(d[3])
        : "r"(__float_as_uint(a[0])), "r"(__float_as_uint(a[1])),
          "r"(__float_as_uint(a[2])), "r"(__float_as_uint(a[3])),
          "r"(__float_as_uint(b[0])), "r"(__float_as_uint(b[1])));
}
__device__ __forceinline__ void mma_bf16(float* d, const uint32_t* a, const uint32_t* b) {
    asm volatile(
        "mma.sync.aligned.m16n8k16.row.col.f32.bf16.bf16.f32 "
        "{%0,%1,%2,%3}, {%4,%5,%6,%7}, {%8,%9}, {%0,%1,%2,%3};"
        : "+f"(d[0]), "+f"(d[1]), "+f"(d[2]), "+f"(d[3])
        : "r"(a[0]), "r"(a[1]), "r"(a[2]), "r"(a[3]), "r"(b[0]), "r"(b[1]));
}
#define CP16(smaddr, gptr) \
    asm volatile("cp.async.cg.shared.global [%0], [%1], 16;" :: "r"(smaddr), "l"(gptr) : "memory")
#define CP_COMMIT() asm volatile("cp.async.commit_group;" ::: "memory")
#define CP_WAIT(n)  asm volatile("cp.async.wait_group %0;" :: "n"(n) : "memory")

// ===========================================================================
// tf32x4 GEMM with per-chunk Neumaier-compensated accumulation.
// C = A @ B^T (+bias)(relu?). Tile 128x64, 256 thr (8 warps, 32x32 warp tile).
// Stage layout (floats): Ah[128*36] Al[128*36] Bh[64*36] Bl[64*36] = 13824.
// ===========================================================================
#define TF32C_SMEM (3 * 13824 * 4)

__global__ void __launch_bounds__(256)
gemm_tf32c(const float* __restrict__ pAh, const float* __restrict__ pAl,
           const float* __restrict__ pBh, const float* __restrict__ pBl,
           const float* __restrict__ bias,
           float* __restrict__ outF, float* __restrict__ outH, float* __restrict__ outL,
           int M, int N, int K, int doRelu)
{
    extern __shared__ float sm[];
    const int tid  = threadIdx.x;
    const int lane = tid & 31, wid = tid >> 5;
    const int g = lane >> 2, q = lane & 3;
    const int warpM = (wid & 3) * 32, warpN = (wid >> 2) * 32;
    const int brow = blockIdx.y * 128, bcol = blockIdx.x * 64;
    const int nch = K >> 5;
    const uint32_t smb = smem_u32(sm);

    float sum[2][4][4], comp[2][4][4];
    #pragma unroll
    for (int i = 0; i < 2; i++)
        #pragma unroll
        for (int j = 0; j < 4; j++)
            #pragma unroll
            for (int r = 0; r < 4; r++) { sum[i][j][r] = 0.f; comp[i][j][r] = 0.f; }

    auto issue = [&](int ch, int s) {
        int kt = ch << 5;
        uint32_t sbase = smb + (uint32_t)s * 13824u * 4u;
        const float* gpA[2] = {pAh, pAl};
        const float* gpB[2] = {pBh, pBl};
        #pragma unroll
        for (int a = 0; a < 2; a++) {
            uint32_t base = sbase + (uint32_t)a * 4608u * 4u;
            #pragma unroll
            for (int it = 0; it < 4; it++) {
                int id = it * 256 + tid;
                int row = id >> 3, seg = id & 7;
                CP16(base + (uint32_t)(row * 144 + seg * 16),
                     gpA[a] + (size_t)(brow + row) * K + kt + seg * 4);
            }
        }
        #pragma unroll
        for (int a = 0; a < 2; a++) {
            uint32_t base = sbase + 9216u * 4u + (uint32_t)a * 2304u * 4u;
            #pragma unroll
            for (int it = 0; it < 2; it++) {
                int id = it * 256 + tid;
                int row = id >> 3, seg = id & 7;
                CP16(base + (uint32_t)(row * 144 + seg * 16),
                     gpB[a] + (size_t)(bcol + row) * K + kt + seg * 4);
            }
        }
        CP_COMMIT();
    };

    issue(0, 0);
    if (nch > 1) issue(1, 1); else CP_COMMIT();
    if (nch > 2) issue(2, 2); else CP_COMMIT();

    for (int c = 0; c < nch; c++) {
        int s = c % 3;
        CP_WAIT(2);
        __syncthreads();

        const float* sAh = sm + s * 13824;
        const float* sAl = sAh + 4608;
        const float* sBh = sAh + 9216;
        const float* sBl = sAh + 11520;

        float acc[2][4][4];
        #pragma unroll
        for (int i = 0; i < 2; i++)
            #pragma unroll
            for (int j = 0; j < 4; j++)
                #pragma unroll
                for (int r = 0; r < 4; r++) acc[i][j][r] = 0.f;

        #pragma unroll
        for (int kb = 0; kb < 32; kb += 8) {
            float ah[2][4], al[2][4], bh[4][2], bl[4][2];
            #pragma unroll
            for (int i = 0; i < 2; i++) {
                int r0 = (warpM + i * 16 + g) * 36 + kb + q;
                ah[i][0] = sAh[r0];       ah[i][1] = sAh[r0 + 288];
                ah[i][2] = sAh[r0 + 4];   ah[i][3] = sAh[r0 + 292];
                al[i][0] = sAl[r0];       al[i][1] = sAl[r0 + 288];
                al[i][2] = sAl[r0 + 4];   al[i][3] = sAl[r0 + 292];
            }
            #pragma unroll
            for (int j = 0; j < 4; j++) {
                int rn = (warpN + j * 8 + g) * 36 + kb + q;
                bh[j][0] = sBh[rn];  bh[j][1] = sBh[rn + 4];
                bl[j][0] = sBl[rn];  bl[j][1] = sBl[rn + 4];
            }
            #pragma unroll
            for (int i = 0; i < 2; i++)
                #pragma unroll
                for (int j = 0; j < 4; j++) {
                    mma_tf32(acc[i][j], ah[i], bh[j]);
                    mma_tf32(acc[i][j], ah[i], bl[j]);
                    mma_tf32(acc[i][j], al[i], bh[j]);
                    mma_tf32(acc[i][j], al[i], bl[j]);
                }
        }

        // Neumaier fold of this chunk into (sum, comp)
        #pragma unroll
        for (int i = 0; i < 2; i++)
            #pragma unroll
            for (int j = 0; j < 4; j++)
                #pragma unroll
                for (int r = 0; r < 4; r++) {
                    float v = acc[i][j][r];
                    float so = sum[i][j][r];
                    float t = so + v;
                    float e = (fabsf(so) >= fabsf(v)) ? ((so - t) + v) : ((v - t) + so);
                    comp[i][j][r] += e;
                    sum[i][j][r] = t;
                }

        __syncthreads();
        if (c + 3 < nch) issue(c + 3, s); else CP_COMMIT();
    }

    #pragma unroll
    for (int i = 0; i < 2; i++) {
        int r0 = brow + warpM + i * 16 + g;
        #pragma unroll
        for (int j = 0; j < 4; j++) {
            int col = bcol + warpN + j * 8 + 2 * q;
            float b0 = 0.f, b1 = 0.f;
            if (bias) { b0 = __ldg(bias + col); b1 = __ldg(bias + col + 1); }
            float v00 = (sum[i][j][0] + comp[i][j][0]) + b0;
            float v01 = (sum[i][j][1] + comp[i][j][1]) + b1;
            float v10 = (sum[i][j][2] + comp[i][j][2]) + b0;
            float v11 = (sum[i][j][3] + comp[i][j][3]) + b1;
            if (doRelu) {
                v00 = fmaxf(v00, 0.f); v01 = fmaxf(v01, 0.f);
                v10 = fmaxf(v10, 0.f); v11 = fmaxf(v11, 0.f);
            }
            size_t o0 = (size_t)r0 * N + col, o1 = o0 + 8 * (size_t)N;
            if (outF) {
                *reinterpret_cast<float2*>(outF + o0) = make_float2(v00, v01);
                *reinterpret_cast<float2*>(outF + o1) = make_float2(v10, v11);
            }
            if (outH) {
                float h00, l00, h01, l01, h10, l10, h11, l11;
                split_tf32(v00, h00, l00); split_tf32(v01, h01, l01);
                split_tf32(v10, h10, l10); split_tf32(v11, h11, l11);
                *reinterpret_cast<float2*>(outH + o0) = make_float2(h00, h01);
                *reinterpret_cast<float2*>(outH + o1) = make_float2(h10, h11);
                *reinterpret_cast<float2*>(outL + o0) = make_float2(l00, l01);
                *reinterpret_cast<float2*>(outL + o1) = make_float2(l10, l11);
            }
        }
    }
}

// ===========================================================================
// bf16 3-product GEMM: decoder layers (validated at 5.9e-6 in R3).
// ===========================================================================
#define BF16_SMEM (12 * 5120 * 2)

__global__ void __launch_bounds__(128)
gemm_bf16(const __nv_bfloat16* __restrict__ pAh, const __nv_bfloat16* __restrict__ pAl,
          const __nv_bfloat16* __restrict__ pBh, const __nv_bfloat16* __restrict__ pBl,
          const float* __restrict__ bias,
          float* __restrict__ outF,
          __nv_bfloat16* __restrict__ outH, __nv_bfloat16* __restrict__ outL,
          int M, int N, int K, int doRelu)
{
    extern __shared__ __nv_bfloat16 smb16[];
    const int tid  = threadIdx.x;
    const int lane = tid & 31, wid = tid >> 5;
    const int g = lane >> 2, q = lane & 3;
    const int warpM = (wid >> 1) * 64, warpN = (wid & 1) * 64;
    const int brow = blockIdx.y * 128, bcol = blockIdx.x * 128;
    const int nch = K >> 5;
    const uint32_t smb = smem_u32(smb16);

    float acc[4][8][4];
    #pragma unroll
    for (int i = 0; i < 4; i++)
        #pragma unroll
        for (int j = 0; j < 8; j++)
            #pragma unroll
            for (int r = 0; r < 4; r++) acc[i][j][r] = 0.0f;

    const __nv_bfloat16* gp[4] = {pAh, pAl, pBh, pBl};
    const int rb[4] = {brow, brow, bcol, bcol};

    auto issue = [&](int ch, int s) {
        int kt = ch << 5;
        #pragma unroll
        for (int a = 0; a < 4; a++) {
            uint32_t base = smb + (uint32_t)(s * 4 + a) * 5120u * 2u;
            #pragma unroll
            for (int it = 0; it < 4; it++) {
                int id = it * 128 + tid;
                int row = id >> 2, seg = id & 3;
                const __nv_bfloat16* src = gp[a] + (size_t)(rb[a] + row) * K + kt + seg * 8;
                CP16(base + (uint32_t)(row * 80 + seg * 16), src);
            }
        }
        CP_COMMIT();
    };

    issue(0, 0);
    if (nch > 1) issue(1, 1); else CP_COMMIT();
    if (nch > 2) issue(2, 2); else CP_COMMIT();

    for (int c = 0; c < nch; c++) {
        int s = c % 3;
        CP_WAIT(2);
        __syncthreads();

        const __nv_bfloat16* sAh = smb16 + (s * 4 + 0) * 5120;
        const __nv_bfloat16* sAl = smb16 + (s * 4 + 1) * 5120;
        const __nv_bfloat16* sBh = smb16 + (s * 4 + 2) * 5120;
        const __nv_bfloat16* sBl = smb16 + (s * 4 + 3) * 5120;

        #pragma unroll
        for (int kb = 0; kb < 32; kb += 16) {
            uint32_t ah[4][4], al[4][4], bh[8][2], bl[8][2];
            #pragma unroll
            for (int i = 0; i < 4; i++) {
                int e0 = (warpM + i * 16 + g) * 40 + kb + 2 * q;
                ah[i][0] = *reinterpret_cast<const uint32_t*>(sAh + e0);
                ah[i][1] = *reinterpret_cast<const uint32_t*>(sAh + e0 + 320);
                ah[i][2] = *reinterpret_cast<const uint32_t*>(sAh + e0 + 8);
                ah[i][3] = *reinterpret_cast<const uint32_t*>(sAh + e0 + 328);
                al[i][0] = *reinterpret_cast<const uint32_t*>(sAl + e0);
                al[i][1] = *reinterpret_cast<const uint32_t*>(sAl + e0 + 320);
                al[i][2] = *reinterpret_cast<const uint32_t*>(sAl + e0 + 8);
                al[i][3] = *reinterpret_cast<const uint32_t*>(sAl + e0 + 328);
            }
            #pragma unroll
            for (int j = 0; j < 8; j++) {
                int en = (warpN + j * 8 + g) * 40 + kb + 2 * q;
                bh[j][0] = *reinterpret_cast<const uint32_t*>(sBh + en);
                bh[j][1] = *reinterpret_cast<const uint32_t*>(sBh + en + 8);
                bl[j][0] = *reinterpret_cast<const uint32_t*>(sBl + en);
                bl[j][1] = *reinterpret_cast<const uint32_t*>(sBl + en + 8);
            }
            #pragma unroll
            for (int i = 0; i < 4; i++)
                #pragma unroll
                for (int j = 0; j < 8; j++) {
                    mma_bf16(acc[i][j], ah[i], bh[j]);
                    mma_bf16(acc[i][j], ah[i], bl[j]);
                    mma_bf16(acc[i][j], al[i], bh[j]);
                }
        }
        __syncthreads();
        if (c + 3 < nch) issue(c + 3, s); else CP_COMMIT();
    }

    #pragma unroll
    for (int i = 0; i < 4; i++) {
        int r0 = brow + warpM + i * 16 + g;
        #pragma unroll
        for (int j = 0; j < 8; j++) {
            int col = bcol + warpN + j * 8 + 2 * q;
            float b0 = 0.f, b1 = 0.f;
            if (bias) { b0 = __ldg(bias + col); b1 = __ldg(bias + col + 1); }
            float v00 = acc[i][j][0] + b0, v01 = acc[i][j][1] + b1;
            float v10 = acc[i][j][2] + b0, v11 = acc[i][j][3] + b1;
            if (doRelu) {
                v00 = fmaxf(v00, 0.f); v01 = fmaxf(v01, 0.f);
                v10 = fmaxf(v10, 0.f); v11 = fmaxf(v11, 0.f);
            }
            size_t o0 = (size_t)r0 * N + col, o1 = o0 + 8 * (size_t)N;
            if (outF) {
                *reinterpret_cast<float2*>(outF + o0) = make_float2(v00, v01);
                *reinterpret_cast<float2*>(outF + o1) = make_float2(v10, v11);
            }
            if (outH) {
                __nv_bfloat16 h[4], l[4];
                split_bf16(v00, h[0], l[0]); split_bf16(v01, h[1], l[1]);
                split_bf16(v10, h[2], l[2]); split_bf16(v11, h[3], l[3]);
                *reinterpret_cast<__nv_bfloat162*>(outH + o0) = __nv_bfloat162(h[0], h[1]);
                *reinterpret_cast<__nv_bfloat162*>(outH + o1) = __nv_bfloat162(h[2], h[3]);
                *reinterpret_cast<__nv_bfloat162*>(outL + o0) = __nv_bfloat162(l[0], l[1]);
                *reinterpret_cast<__nv_bfloat162*>(outL + o1) = __nv_bfloat162(l[2], l[3]);
            }
        }
    }
}

// ---------------- prep kernels ----------------
__global__ void esplit_tf32(const float* __restrict__ a, float* __restrict__ hi,
                            float* __restrict__ lo, int n4)
{
    int i = blockIdx.x * blockDim.x + threadIdx.x;
    if (i >= n4) return;
    float4 v = reinterpret_cast<const float4*>(a)[i];
    float4 h, l;
    split_tf32(v.x, h.x, l.x); split_tf32(v.y, h.y, l.y);
    split_tf32(v.z, h.z, l.z); split_tf32(v.w, h.w, l.w);
    reinterpret_cast<float4*>(hi)[i] = h;
    reinterpret_cast<float4*>(lo)[i] = l;
}

__global__ void emb_split(const float* __restrict__ a, float* __restrict__ hi,
                          float* __restrict__ lo, __nv_bfloat16* __restrict__ bh,
                          __nv_bfloat16* __restrict__ bl, int n2)
{
    int i = blockIdx.x * blockDim.x + threadIdx.x;
    if (i >= n2) return;
    float2 v = reinterpret_cast<const float2*>(a)[i];
    float2 h, l;
    split_tf32(v.x, h.x, l.x); split_tf32(v.y, h.y, l.y);
    reinterpret_cast<float2*>(hi)[i] = h;
    reinterpret_cast<float2*>(lo)[i] = l;
    __nv_bfloat16 bhx, blx, bhy, bly;
    split_bf16(v.x, bhx, blx); split_bf16(v.y, bhy, bly);
    reinterpret_cast<__nv_bfloat162*>(bh)[i] = __nv_bfloat162(bhx, bhy);
    reinterpret_cast<__nv_bfloat162*>(bl)[i] = __nv_bfloat162(blx, bly);
}

__global__ void wt_split_tf32(const float* __restrict__ W, float* __restrict__ hi,
                              float* __restrict__ lo, int Kd, int N)
{
    __shared__ float t[32][33];
    int bx = blockIdx.x * 32, by = blockIdx.y * 32;
    for (int i = threadIdx.y; i < 32; i += 8)
        t[i][threadIdx.x] = W[(size_t)(by + i) * N + bx + threadIdx.x];
    __syncthreads();
    for (int i = threadIdx.y; i < 32; i += 8) {
        float v = t[threadIdx.x][i];
        float h, l;
        split_tf32(v, h, l);
        size_t o = (size_t)(bx + i) * Kd + by + threadIdx.x;
        hi[o] = h; lo[o] = l;
    }
}

__global__ void wt_split_bf16(const float* __restrict__ W, __nv_bfloat16* __restrict__ hi,
                              __nv_bfloat16* __restrict__ lo, int Kd, int N)
{
    __shared__ float t[32][33];
    int bx = blockIdx.x * 32, by = blockIdx.y * 32;
    for (int i = threadIdx.y; i < 32; i += 8)
        t[i][threadIdx.x] = W[(size_t)(by + i) * N + bx + threadIdx.x];
    __syncthreads();
    for (int i = threadIdx.y; i < 32; i += 8) {
        float v = t[threadIdx.x][i];
        __nv_bfloat16 h, l;
        split_bf16(v, h, l);
        size_t o = (size_t)(bx + i) * Kd + by + threadIdx.x;
        hi[o] = h; lo[o] = l;
    }
}

__global__ void c2_kernel(const float* __restrict__ c, float* __restrict__ c2)
{
    int k = blockIdx.x * 8 + (threadIdx.x >> 5);
    int lane = threadIdx.x & 31;
    float s = 0.0f;
    for (int d = lane; d < D_EMB; d += 32) {
        float v = c[(size_t)k * D_EMB + d];
        s = fmaf(v, v, s);
    }
    #pragma unroll
    for (int o = 16; o; o >>= 1) s += __shfl_xor_sync(0xFFFFFFFFu, s, o);
    if (lane == 0) c2[k] = s;
}

__global__ void argmin_labels(const float* __restrict__ emb, const float* __restrict__ S,
                              const float* __restrict__ c2, float* __restrict__ labels)
{
    const int row = blockIdx.x, tid = threadIdx.x;
    __shared__ float red[256];
    float v = emb[(size_t)row * D_EMB + tid];
    red[tid] = v * v;
    __syncthreads();
    #pragma unroll
    for (int s = 128; s > 0; s >>= 1) {
        if (tid < s) red[tid] += red[tid + s];
        __syncthreads();
    }
    const float e2 = red[0];
    __syncthreads();
    float best = 3.402823466e38f;
    int bi = 0;
    for (int k = tid; k < K_CENT; k += 256) {
        float d = fmaxf(e2 + c2[k] - 2.0f * S[(size_t)row * K_CENT + k], 0.0f);
        if (d < best) { best = d; bi = k; }
    }
    __shared__ float sv[256];
    __shared__ int si[256];
    sv[tid] = best; si[tid] = bi;
    __syncthreads();
    #pragma unroll
    for (int s = 128; s > 0; s >>= 1) {
        if (tid < s) {
            float v2 = sv[tid + s]; int i2 = si[tid + s];
            if (v2 < sv[tid] || (v2 == sv[tid] && i2 < si[tid])) { sv[tid] = v2; si[tid] = i2; }
        }
        __syncthreads();
    }
    const int win = si[0];
    for (int k = tid; k < K_CENT; k += 256)
        labels[(size_t)row * K_CENT + k] = (k == win) ? 1.0f : 0.0f;
}

// ---------------- host launcher ----------------
extern "C" void kernel_launch(void* const* d_in, const int* in_sizes, int n_in,
                              void* d_out, int out_size)
{
    (void)in_sizes; (void)n_in; (void)out_size;

    cudaFuncSetAttribute(gemm_tf32c, cudaFuncAttributeMaxDynamicSharedMemorySize, TF32C_SMEM);
    cudaFuncSetAttribute(gemm_bf16,  cudaFuncAttributeMaxDynamicSharedMemorySize, BF16_SMEM);

    const float* x = (const float*)d_in[0];
    const float* W[8]  = {(const float*)d_in[1],  (const float*)d_in[3],
                          (const float*)d_in[5],  (const float*)d_in[7],
                          (const float*)d_in[9],  (const float*)d_in[11],
                          (const float*)d_in[13], (const float*)d_in[15]};
    const float* bv[8] = {(const float*)d_in[2],  (const float*)d_in[4],
                          (const float*)d_in[6],  (const float*)d_in[8],
                          (const float*)d_in[10], (const float*)d_in[12],
                          (const float*)d_in[14], (const float*)d_in[16]};
    const float* centers = (const float*)d_in[17];

    float* out    = (float*)d_out;
    float* recon  = out;
    float* emb    = out + (size_t)B_ROWS * D_IN;
    float* labels = emb + (size_t)B_ROWS * D_EMB;

    float *xh, *xl, *h0h, *h0l, *h1h, *h1l, *eh, *el, *wh, *wl, *ch, *cl, *c2;
    __nv_bfloat16 *ebh, *ebl, *wbh, *wbl, *d0h, *d0l, *d1h, *d1l;
    cudaGetSymbolAddress((void**)&xh, g_xh);   cudaGetSymbolAddress((void**)&xl, g_xl);
    cudaGetSymbolAddress((void**)&h0h, g_h0h); cudaGetSymbolAddress((void**)&h0l, g_h0l);
    cudaGetSymbolAddress((void**)&h1h, g_h1h); cudaGetSymbolAddress((void**)&h1l, g_h1l);
    cudaGetSymbolAddress((void**)&eh, g_eh);   cudaGetSymbolAddress((void**)&el, g_el);
    cudaGetSymbolAddress((void**)&wh, g_wh);   cudaGetSymbolAddress((void**)&wl, g_wl);
    cudaGetSymbolAddress((void**)&ch, g_ch);   cudaGetSymbolAddress((void**)&cl, g_cl);
    cudaGetSymbolAddress((void**)&c2, g_c2);
    cudaGetSymbolAddress((void**)&ebh, g_ebh); cudaGetSymbolAddress((void**)&ebl, g_ebl);
    cudaGetSymbolAddress((void**)&wbh, g_wbh); cudaGetSymbolAddress((void**)&wbl, g_wbl);
    cudaGetSymbolAddress((void**)&d0h, g_d0h); cudaGetSymbolAddress((void**)&d0l, g_d0l);
    cudaGetSymbolAddress((void**)&d1h, g_d1h); cudaGetSymbolAddress((void**)&d1l, g_d1l);

    const int fi[8] = {1024, 2048, 1024, 512, 256, 512, 1024, 2048};
    const int fo[8] = {2048, 1024, 512, 256, 512, 1024, 2048, 1024};
    size_t off[8], acc = 0, accd = 0;
    for (int i = 0; i < 4; i++) { off[i] = acc;  acc  += (size_t)fi[i] * fo[i]; }
    for (int i = 4; i < 8; i++) { off[i] = accd; accd += (size_t)fi[i] * fo[i]; }

    // ---- prep ----
    esplit_tf32<<<(B_ROWS * D_IN / 4 + 255) / 256, 256>>>(x, xh, xl, B_ROWS * D_IN / 4);
    esplit_tf32<<<(K_CENT * D_EMB / 4 + 255) / 256, 256>>>(centers, ch, cl, K_CENT * D_EMB / 4);
    c2_kernel<<<K_CENT / 8, 256>>>(centers, c2);
    for (int i = 0; i < 4; i++) {
        dim3 g(fo[i] / 32, fi[i] / 32), b(32, 8);
        wt_split_tf32<<<g, b>>>(W[i], wh + off[i], wl + off[i], fi[i], fo[i]);
    }
    for (int i = 4; i < 8; i++) {
        dim3 g(fo[i] / 32, fi[i] / 32), b(32, 8);
        wt_split_bf16<<<g, b>>>(W[i], wbh + off[i], wbl + off[i], fi[i], fo[i]);
    }

    // ---- encoder (tf32x4 + Neumaier) ----
    {
        dim3 g0(2048 / 64, B_ROWS / 128);
        gemm_tf32c<<<g0, 256, TF32C_SMEM>>>(xh, xl, wh + off[0], wl + off[0], bv[0],
                                            nullptr, h0h, h0l, B_ROWS, 2048, 1024, 1);
        dim3 g1(1024 / 64, B_ROWS / 128);
        gemm_tf32c<<<g1, 256, TF32C_SMEM>>>(h0h, h0l, wh + off[1], wl + off[1], bv[1],
                                            nullptr, h1h, h1l, B_ROWS, 1024, 2048, 1);
        dim3 g2(512 / 64, B_ROWS / 128);
        gemm_tf32c<<<g2, 256, TF32C_SMEM>>>(h1h, h1l, wh + off[2], wl + off[2], bv[2],
                                            nullptr, h0h, h0l, B_ROWS, 512, 1024, 1);
        dim3 g3(256 / 64, B_ROWS / 128);
        gemm_tf32c<<<g3, 256, TF32C_SMEM>>>(h0h, h0l, wh + off[3], wl + off[3], bv[3],
                                            emb, nullptr, nullptr, B_ROWS, 256, 512, 0);
    }
    emb_split<<<(B_ROWS * D_EMB / 2 + 255) / 256, 256>>>(emb, eh, el, ebh, ebl,
                                                         B_ROWS * D_EMB / 2);
    // ---- clustering ----
    {
        dim3 g(K_CENT / 64, B_ROWS / 128);
        gemm_tf32c<<<g, 256, TF32C_SMEM>>>(eh, el, ch, cl, nullptr,
                                           h1h, nullptr, nullptr, B_ROWS, K_CENT, D_EMB, 0);
    }
    argmin_labels<<<B_ROWS, 256>>>(emb, h1h, c2, labels);

    // ---- decoder (bf16x3) ----
    {
        dim3 g0(512 / 128, B_ROWS / 128);
        gemm_bf16<<<g0, 128, BF16_SMEM>>>(ebh, ebl, wbh + off[4], wbl + off[4], bv[4],
                                          nullptr, d0h, d0l, B_ROWS, 512, 256, 1);
        dim3 g1(1024 / 128, B_ROWS / 128);
        gemm_bf16<<<g1, 128, BF16_SMEM>>>(d0h, d0l, wbh + off[5], wbl + off[5], bv[5],
                                          nullptr, d1h, d1l, B_ROWS, 1024, 512, 1);
        dim3 g2(2048 / 128, B_ROWS / 128);
        gemm_bf16<<<g2, 128, BF16_SMEM>>>(d1h, d1l, wbh + off[6], wbl + off[6], bv[6],
                                          nullptr, d0h, d0l, B_ROWS, 2048, 1024, 1);
        dim3 g3(1024 / 128, B_ROWS / 128);
        gemm_bf16<<<g3, 128, BF16_SMEM>>>(d0h, d0l, wbh + off[7], wbl + off[7], bv[7],
                                          recon, nullptr, nullptr, B_ROWS, 1024, 2048, 0);
    }
}

// round 6
// speedup vs baseline: 2.0915x; 1.0837x over previous
#include <cuda_runtime.h>
#include <cuda_bf16.h>
#include <cstdint>
#include <cstddef>

#define B_ROWS 8192
#define D_IN   1024
#define D_EMB  256
#define K_CENT 1024
#define WSUM   4849664

// ---------------- device scratch ----------------
__device__ __align__(16) float g_xh[(size_t)B_ROWS * D_IN];
__device__ __align__(16) float g_xl[(size_t)B_ROWS * D_IN];
__device__ __align__(16) float g_h0h[(size_t)B_ROWS * 2048];
__device__ __align__(16) float g_h0l[(size_t)B_ROWS * 2048];
__device__ __align__(16) float g_h1h[(size_t)B_ROWS * 2048];
__device__ __align__(16) float g_h1l[(size_t)B_ROWS * 2048];
__device__ __align__(16) float g_eh[(size_t)B_ROWS * D_EMB];
__device__ __align__(16) float g_el[(size_t)B_ROWS * D_EMB];
__device__ __align__(16) __nv_bfloat16 g_ebh[(size_t)B_ROWS * D_EMB];
__device__ __align__(16) __nv_bfloat16 g_ebl[(size_t)B_ROWS * D_EMB];
__device__ __align__(16) float g_wh[WSUM];
__device__ __align__(16) float g_wl[WSUM];
__device__ __align__(16) __nv_bfloat16 g_wbh[WSUM];
__device__ __align__(16) __nv_bfloat16 g_wbl[WSUM];
__device__ __align__(16) float g_ch[K_CENT * D_EMB];
__device__ __align__(16) float g_cl[K_CENT * D_EMB];
__device__ __align__(16) __nv_bfloat16 g_d0h[(size_t)B_ROWS * 2048];
__device__ __align__(16) __nv_bfloat16 g_d0l[(size_t)B_ROWS * 2048];
__device__ __align__(16) __nv_bfloat16 g_d1h[(size_t)B_ROWS * 2048];
__device__ __align__(16) __nv_bfloat16 g_d1l[(size_t)B_ROWS * 2048];
__device__ float g_c2[K_CENT];

// ---------------- helpers ----------------
__device__ __forceinline__ uint32_t smem_u32(const void* p) {
    uint32_t a;
    asm("{ .reg .u64 t; cvta.to.shared.u64 t, %1; cvt.u32.u64 %0, t; }" : "=r"(a) : "l"(p));
    return a;
}
__device__ __forceinline__ void split_tf32(float v, float& h, float& l) {
    uint32_t u;
    asm("cvt.rna.tf32.f32 %0, %1;" : "=r"(u) : "f"(v));
    h = __uint_as_float(u);
    float r = v - h;
    asm("cvt.rna.tf32.f32 %0, %1;" : "=r"(u) : "f"(r));
    l = __uint_as_float(u);
}
__device__ __forceinline__ void split_bf16(float v, __nv_bfloat16& h, __nv_bfloat16& l) {
    h = __float2bfloat16(v);
    l = __float2bfloat16(v - __bfloat162float(h));
}
__device__ __forceinline__ void mma_tf32(float* d, const float* a, const float* b) {
    asm volatile(
        "mma.sync.aligned.m16n8k8.row.col.f32.tf32.tf32.f32 "
        "{%0,%1,%2,%3}, {%4,%5,%6,%7}, {%8,%9}, {%0,%1,%2,%3};"
        : "+f"(d[0]), "+f"(d[1]), "+f"(d[2]), "+f"(d[3])
        : "r"(__float_as_uint(a[0])), "r"(__float_as_uint(a[1])),
          "r"(__float_as_uint(a[2])), "r"(__float_as_uint(a[3])),
          "r"(__float_as_uint(b[0])), "r"(__float_as_uint(b[1])));
}
__device__ __forceinline__ void mma_bf16(float* d, const uint32_t* a, const uint32_t* b) {
    asm volatile(
        "mma.sync.aligned.m16n8k16.row.col.f32.bf16.bf16.f32 "
        "{%0,%1,%2,%3}, {%4,%5,%6,%7}, {%8,%9}, {%0,%1,%2,%3};"
        : "+f"(d[0]), "+f"(d[1]), "+f"(d[2]), "+f"(d[3])
        : "r"(a[0]), "r"(a[1]), "r"(a[2]), "r"(a[3]), "r"(b[0]), "r"(b[1]));
}
#define CP16(smaddr, gptr) \
    asm volatile("cp.async.cg.shared.global [%0], [%1], 16;" :: "r"(smaddr), "l"(gptr) : "memory")
#define CP_COMMIT() asm volatile("cp.async.commit_group;" ::: "memory")
#define CP_WAIT(n)  asm volatile("cp.async.wait_group %0;" :: "n"(n) : "memory")

// ===========================================================================
// tf32x3 GEMM (hh + hl + lh) with per-chunk Neumaier-compensated accumulation.
// C = A @ B^T (+bias)(relu?). Tile 128x64, 256 thr (8 warps, 32x32 warp tile).
// ===========================================================================
#define TF32C_SMEM (3 * 13824 * 4)

__global__ void __launch_bounds__(256)
gemm_tf32c(const float* __restrict__ pAh, const float* __restrict__ pAl,
           const float* __restrict__ pBh, const float* __restrict__ pBl,
           const float* __restrict__ bias,
           float* __restrict__ outF, float* __restrict__ outH, float* __restrict__ outL,
           int M, int N, int K, int doRelu)
{
    extern __shared__ float sm[];
    const int tid  = threadIdx.x;
    const int lane = tid & 31, wid = tid >> 5;
    const int g = lane >> 2, q = lane & 3;
    const int warpM = (wid & 3) * 32, warpN = (wid >> 2) * 32;
    const int brow = blockIdx.y * 128, bcol = blockIdx.x * 64;
    const int nch = K >> 5;
    const uint32_t smb = smem_u32(sm);

    float sum[2][4][4], comp[2][4][4];
    #pragma unroll
    for (int i = 0; i < 2; i++)
        #pragma unroll
        for (int j = 0; j < 4; j++)
            #pragma unroll
            for (int r = 0; r < 4; r++) { sum[i][j][r] = 0.f; comp[i][j][r] = 0.f; }

    auto issue = [&](int ch, int s) {
        int kt = ch << 5;
        uint32_t sbase = smb + (uint32_t)s * 13824u * 4u;
        const float* gpA[2] = {pAh, pAl};
        const float* gpB[2] = {pBh, pBl};
        #pragma unroll
        for (int a = 0; a < 2; a++) {
            uint32_t base = sbase + (uint32_t)a * 4608u * 4u;
            #pragma unroll
            for (int it = 0; it < 4; it++) {
                int id = it * 256 + tid;
                int row = id >> 3, seg = id & 7;
                CP16(base + (uint32_t)(row * 144 + seg * 16),
                     gpA[a] + (size_t)(brow + row) * K + kt + seg * 4);
            }
        }
        #pragma unroll
        for (int a = 0; a < 2; a++) {
            uint32_t base = sbase + 9216u * 4u + (uint32_t)a * 2304u * 4u;
            #pragma unroll
            for (int it = 0; it < 2; it++) {
                int id = it * 256 + tid;
                int row = id >> 3, seg = id & 7;
                CP16(base + (uint32_t)(row * 144 + seg * 16),
                     gpB[a] + (size_t)(bcol + row) * K + kt + seg * 4);
            }
        }
        CP_COMMIT();
    };

    issue(0, 0);
    if (nch > 1) issue(1, 1); else CP_COMMIT();
    if (nch > 2) issue(2, 2); else CP_COMMIT();

    for (int c = 0; c < nch; c++) {
        int s = c % 3;
        CP_WAIT(2);
        __syncthreads();

        const float* sAh = sm + s * 13824;
        const float* sAl = sAh + 4608;
        const float* sBh = sAh + 9216;
        const float* sBl = sAh + 11520;

        float acc[2][4][4];
        #pragma unroll
        for (int i = 0; i < 2; i++)
            #pragma unroll
            for (int j = 0; j < 4; j++)
                #pragma unroll
                for (int r = 0; r < 4; r++) acc[i][j][r] = 0.f;

        #pragma unroll
        for (int kb = 0; kb < 32; kb += 8) {
            float ah[2][4], al[2][4], bh[4][2], bl[4][2];
            #pragma unroll
            for (int i = 0; i < 2; i++) {
                int r0 = (warpM + i * 16 + g) * 36 + kb + q;
                ah[i][0] = sAh[r0];       ah[i][1] = sAh[r0 + 288];
                ah[i][2] = sAh[r0 + 4];   ah[i][3] = sAh[r0 + 292];
                al[i][0] = sAl[r0];       al[i][1] = sAl[r0 + 288];
                al[i][2] = sAl[r0 + 4];   al[i][3] = sAl[r0 + 292];
            }
            #pragma unroll
            for (int j = 0; j < 4; j++) {
                int rn = (warpN + j * 8 + g) * 36 + kb + q;
                bh[j][0] = sBh[rn];  bh[j][1] = sBh[rn + 4];
                bl[j][0] = sBl[rn];  bl[j][1] = sBl[rn + 4];
            }
            #pragma unroll
            for (int i = 0; i < 2; i++)
                #pragma unroll
                for (int j = 0; j < 4; j++) {
                    mma_tf32(acc[i][j], ah[i], bh[j]);
                    mma_tf32(acc[i][j], ah[i], bl[j]);
                    mma_tf32(acc[i][j], al[i], bh[j]);
                }
        }

        // Neumaier fold of this chunk into (sum, comp)
        #pragma unroll
        for (int i = 0; i < 2; i++)
            #pragma unroll
            for (int j = 0; j < 4; j++)
                #pragma unroll
                for (int r = 0; r < 4; r++) {
                    float v = acc[i][j][r];
                    float so = sum[i][j][r];
                    float t = so + v;
                    float e = (fabsf(so) >= fabsf(v)) ? ((so - t) + v) : ((v - t) + so);
                    comp[i][j][r] += e;
                    sum[i][j][r] = t;
                }

        __syncthreads();
        if (c + 3 < nch) issue(c + 3, s); else CP_COMMIT();
    }

    #pragma unroll
    for (int i = 0; i < 2; i++) {
        int r0 = brow + warpM + i * 16 + g;
        #pragma unroll
        for (int j = 0; j < 4; j++) {
            int col = bcol + warpN + j * 8 + 2 * q;
            float b0 = 0.f, b1 = 0.f;
            if (bias) { b0 = __ldg(bias + col); b1 = __ldg(bias + col + 1); }
            float v00 = (sum[i][j][0] + comp[i][j][0]) + b0;
            float v01 = (sum[i][j][1] + comp[i][j][1]) + b1;
            float v10 = (sum[i][j][2] + comp[i][j][2]) + b0;
            float v11 = (sum[i][j][3] + comp[i][j][3]) + b1;
            if (doRelu) {
                v00 = fmaxf(v00, 0.f); v01 = fmaxf(v01, 0.f);
                v10 = fmaxf(v10, 0.f); v11 = fmaxf(v11, 0.f);
            }
            size_t o0 = (size_t)r0 * N + col, o1 = o0 + 8 * (size_t)N;
            if (outF) {
                *reinterpret_cast<float2*>(outF + o0) = make_float2(v00, v01);
                *reinterpret_cast<float2*>(outF + o1) = make_float2(v10, v11);
            }
            if (outH) {
                float h00, l00, h01, l01, h10, l10, h11, l11;
                split_tf32(v00, h00, l00); split_tf32(v01, h01, l01);
                split_tf32(v10, h10, l10); split_tf32(v11, h11, l11);
                *reinterpret_cast<float2*>(outH + o0) = make_float2(h00, h01);
                *reinterpret_cast<float2*>(outH + o1) = make_float2(h10, h11);
                *reinterpret_cast<float2*>(outL + o0) = make_float2(l00, l01);
                *reinterpret_cast<float2*>(outL + o1) = make_float2(l10, l11);
            }
        }
    }
}

// ===========================================================================
// bf16 3-product GEMM: decoder layers (validated at 5.9e-6).
// ===========================================================================
#define BF16_SMEM (12 * 5120 * 2)

__global__ void __launch_bounds__(128)
gemm_bf16(const __nv_bfloat16* __restrict__ pAh, const __nv_bfloat16* __restrict__ pAl,
          const __nv_bfloat16* __restrict__ pBh, const __nv_bfloat16* __restrict__ pBl,
          const float* __restrict__ bias,
          float* __restrict__ outF,
          __nv_bfloat16* __restrict__ outH, __nv_bfloat16* __restrict__ outL,
          int M, int N, int K, int doRelu)
{
    extern __shared__ __nv_bfloat16 smb16[];
    const int tid  = threadIdx.x;
    const int lane = tid & 31, wid = tid >> 5;
    const int g = lane >> 2, q = lane & 3;
    const int warpM = (wid >> 1) * 64, warpN = (wid & 1) * 64;
    const int brow = blockIdx.y * 128, bcol = blockIdx.x * 128;
    const int nch = K >> 5;
    const uint32_t smb = smem_u32(smb16);

    float acc[4][8][4];
    #pragma unroll
    for (int i = 0; i < 4; i++)
        #pragma unroll
        for (int j = 0; j < 8; j++)
            #pragma unroll
            for (int r = 0; r < 4; r++) acc[i][j][r] = 0.0f;

    const __nv_bfloat16* gp[4] = {pAh, pAl, pBh, pBl};
    const int rb[4] = {brow, brow, bcol, bcol};

    auto issue = [&](int ch, int s) {
        int kt = ch << 5;
        #pragma unroll
        for (int a = 0; a < 4; a++) {
            uint32_t base = smb + (uint32_t)(s * 4 + a) * 5120u * 2u;
            #pragma unroll
            for (int it = 0; it < 4; it++) {
                int id = it * 128 + tid;
                int row = id >> 2, seg = id & 3;
                const __nv_bfloat16* src = gp[a] + (size_t)(rb[a] + row) * K + kt + seg * 8;
                CP16(base + (uint32_t)(row * 80 + seg * 16), src);
            }
        }
        CP_COMMIT();
    };

    issue(0, 0);
    if (nch > 1) issue(1, 1); else CP_COMMIT();
    if (nch > 2) issue(2, 2); else CP_COMMIT();

    for (int c = 0; c < nch; c++) {
        int s = c % 3;
        CP_WAIT(2);
        __syncthreads();

        const __nv_bfloat16* sAh = smb16 + (s * 4 + 0) * 5120;
        const __nv_bfloat16* sAl = smb16 + (s * 4 + 1) * 5120;
        const __nv_bfloat16* sBh = smb16 + (s * 4 + 2) * 5120;
        const __nv_bfloat16* sBl = smb16 + (s * 4 + 3) * 5120;

        #pragma unroll
        for (int kb = 0; kb < 32; kb += 16) {
            uint32_t ah[4][4], al[4][4], bh[8][2], bl[8][2];
            #pragma unroll
            for (int i = 0; i < 4; i++) {
                int e0 = (warpM + i * 16 + g) * 40 + kb + 2 * q;
                ah[i][0] = *reinterpret_cast<const uint32_t*>(sAh + e0);
                ah[i][1] = *reinterpret_cast<const uint32_t*>(sAh + e0 + 320);
                ah[i][2] = *reinterpret_cast<const uint32_t*>(sAh + e0 + 8);
                ah[i][3] = *reinterpret_cast<const uint32_t*>(sAh + e0 + 328);
                al[i][0] = *reinterpret_cast<const uint32_t*>(sAl + e0);
                al[i][1] = *reinterpret_cast<const uint32_t*>(sAl + e0 + 320);
                al[i][2] = *reinterpret_cast<const uint32_t*>(sAl + e0 + 8);
                al[i][3] = *reinterpret_cast<const uint32_t*>(sAl + e0 + 328);
            }
            #pragma unroll
            for (int j = 0; j < 8; j++) {
                int en = (warpN + j * 8 + g) * 40 + kb + 2 * q;
                bh[j][0] = *reinterpret_cast<const uint32_t*>(sBh + en);
                bh[j][1] = *reinterpret_cast<const uint32_t*>(sBh + en + 8);
                bl[j][0] = *reinterpret_cast<const uint32_t*>(sBl + en);
                bl[j][1] = *reinterpret_cast<const uint32_t*>(sBl + en + 8);
            }
            #pragma unroll
            for (int i = 0; i < 4; i++)
                #pragma unroll
                for (int j = 0; j < 8; j++) {
                    mma_bf16(acc[i][j], ah[i], bh[j]);
                    mma_bf16(acc[i][j], ah[i], bl[j]);
                    mma_bf16(acc[i][j], al[i], bh[j]);
                }
        }
        __syncthreads();
        if (c + 3 < nch) issue(c + 3, s); else CP_COMMIT();
    }

    #pragma unroll
    for (int i = 0; i < 4; i++) {
        int r0 = brow + warpM + i * 16 + g;
        #pragma unroll
        for (int j = 0; j < 8; j++) {
            int col = bcol + warpN + j * 8 + 2 * q;
            float b0 = 0.f, b1 = 0.f;
            if (bias) { b0 = __ldg(bias + col); b1 = __ldg(bias + col + 1); }
            float v00 = acc[i][j][0] + b0, v01 = acc[i][j][1] + b1;
            float v10 = acc[i][j][2] + b0, v11 = acc[i][j][3] + b1;
            if (doRelu) {
                v00 = fmaxf(v00, 0.f); v01 = fmaxf(v01, 0.f);
                v10 = fmaxf(v10, 0.f); v11 = fmaxf(v11, 0.f);
            }
            size_t o0 = (size_t)r0 * N + col, o1 = o0 + 8 * (size_t)N;
            if (outF) {
                *reinterpret_cast<float2*>(outF + o0) = make_float2(v00, v01);
                *reinterpret_cast<float2*>(outF + o1) = make_float2(v10, v11);
            }
            if (outH) {
                __nv_bfloat16 h[4], l[4];
                split_bf16(v00, h[0], l[0]); split_bf16(v01, h[1], l[1]);
                split_bf16(v10, h[2], l[2]); split_bf16(v11, h[3], l[3]);
                *reinterpret_cast<__nv_bfloat162*>(outH + o0) = __nv_bfloat162(h[0], h[1]);
                *reinterpret_cast<__nv_bfloat162*>(outH + o1) = __nv_bfloat162(h[2], h[3]);
                *reinterpret_cast<__nv_bfloat162*>(outL + o0) = __nv_bfloat162(l[0], l[1]);
                *reinterpret_cast<__nv_bfloat162*>(outL + o1) = __nv_bfloat162(l[2], l[3]);
            }
        }
    }
}

// ---------------- prep kernels ----------------
__global__ void esplit_tf32(const float* __restrict__ a, float* __restrict__ hi,
                            float* __restrict__ lo, int n4)
{
    int i = blockIdx.x * blockDim.x + threadIdx.x;
    if (i >= n4) return;
    float4 v = reinterpret_cast<const float4*>(a)[i];
    float4 h, l;
    split_tf32(v.x, h.x, l.x); split_tf32(v.y, h.y, l.y);
    split_tf32(v.z, h.z, l.z); split_tf32(v.w, h.w, l.w);
    reinterpret_cast<float4*>(hi)[i] = h;
    reinterpret_cast<float4*>(lo)[i] = l;
}

__global__ void emb_split(const float* __restrict__ a, float* __restrict__ hi,
                          float* __restrict__ lo, __nv_bfloat16* __restrict__ bh,
                          __nv_bfloat16* __restrict__ bl, int n2)
{
    int i = blockIdx.x * blockDim.x + threadIdx.x;
    if (i >= n2) return;
    float2 v = reinterpret_cast<const float2*>(a)[i];
    float2 h, l;
    split_tf32(v.x, h.x, l.x); split_tf32(v.y, h.y, l.y);
    reinterpret_cast<float2*>(hi)[i] = h;
    reinterpret_cast<float2*>(lo)[i] = l;
    __nv_bfloat16 bhx, blx, bhy, bly;
    split_bf16(v.x, bhx, blx); split_bf16(v.y, bhy, bly);
    reinterpret_cast<__nv_bfloat162*>(bh)[i] = __nv_bfloat162(bhx, bhy);
    reinterpret_cast<__nv_bfloat162*>(bl)[i] = __nv_bfloat162(blx, bly);
}

__global__ void wt_split_tf32(const float* __restrict__ W, float* __restrict__ hi,
                              float* __restrict__ lo, int Kd, int N)
{
    __shared__ float t[32][33];
    int bx = blockIdx.x * 32, by = blockIdx.y * 32;
    for (int i = threadIdx.y; i < 32; i += 8)
        t[i][threadIdx.x] = W[(size_t)(by + i) * N + bx + threadIdx.x];
    __syncthreads();
    for (int i = threadIdx.y; i < 32; i += 8) {
        float v = t[threadIdx.x][i];
        float h, l;
        split_tf32(v, h, l);
        size_t o = (size_t)(bx + i) * Kd + by + threadIdx.x;
        hi[o] = h; lo[o] = l;
    }
}

__global__ void wt_split_bf16(const float* __restrict__ W, __nv_bfloat16* __restrict__ hi,
                              __nv_bfloat16* __restrict__ lo, int Kd, int N)
{
    __shared__ float t[32][33];
    int bx = blockIdx.x * 32, by = blockIdx.y * 32;
    for (int i = threadIdx.y; i < 32; i += 8)
        t[i][threadIdx.x] = W[(size_t)(by + i) * N + bx + threadIdx.x];
    __syncthreads();
    for (int i = threadIdx.y; i < 32; i += 8) {
        float v = t[threadIdx.x][i];
        __nv_bfloat16 h, l;
        split_bf16(v, h, l);
        size_t o = (size_t)(bx + i) * Kd + by + threadIdx.x;
        hi[o] = h; lo[o] = l;
    }
}

__global__ void c2_kernel(const float* __restrict__ c, float* __restrict__ c2)
{
    int k = blockIdx.x * 8 + (threadIdx.x >> 5);
    int lane = threadIdx.x & 31;
    float s = 0.0f;
    for (int d = lane; d < D_EMB; d += 32) {
        float v = c[(size_t)k * D_EMB + d];
        s = fmaf(v, v, s);
    }
    #pragma unroll
    for (int o = 16; o; o >>= 1) s += __shfl_xor_sync(0xFFFFFFFFu, s, o);
    if (lane == 0) c2[k] = s;
}

__global__ void argmin_labels(const float* __restrict__ emb, const float* __restrict__ S,
                              const float* __restrict__ c2, float* __restrict__ labels)
{
    const int row = blockIdx.x, tid = threadIdx.x;
    __shared__ float red[256];
    float v = emb[(size_t)row * D_EMB + tid];
    red[tid] = v * v;
    __syncthreads();
    #pragma unroll
    for (int s = 128; s > 0; s >>= 1) {
        if (tid < s) red[tid] += red[tid + s];
        __syncthreads();
    }
    const float e2 = red[0];
    __syncthreads();
    float best = 3.402823466e38f;
    int bi = 0;
    for (int k = tid; k < K_CENT; k += 256) {
        float d = fmaxf(e2 + c2[k] - 2.0f * S[(size_t)row * K_CENT + k], 0.0f);
        if (d < best) { best = d; bi = k; }
    }
    __shared__ float sv[256];
    __shared__ int si[256];
    sv[tid] = best; si[tid] = bi;
    __syncthreads();
    #pragma unroll
    for (int s = 128; s > 0; s >>= 1) {
        if (tid < s) {
            float v2 = sv[tid + s]; int i2 = si[tid + s];
            if (v2 < sv[tid] || (v2 == sv[tid] && i2 < si[tid])) { sv[tid] = v2; si[tid] = i2; }
        }
        __syncthreads();
    }
    const int win = si[0];
    for (int k = tid; k < K_CENT; k += 256)
        labels[(size_t)row * K_CENT + k] = (k == win) ? 1.0f : 0.0f;
}

// ---------------- host launcher ----------------
extern "C" void kernel_launch(void* const* d_in, const int* in_sizes, int n_in,
                              void* d_out, int out_size)
{
    (void)in_sizes; (void)n_in; (void)out_size;

    cudaFuncSetAttribute(gemm_tf32c, cudaFuncAttributeMaxDynamicSharedMemorySize, TF32C_SMEM);
    cudaFuncSetAttribute(gemm_bf16,  cudaFuncAttributeMaxDynamicSharedMemorySize, BF16_SMEM);

    const float* x = (const float*)d_in[0];
    const float* W[8]  = {(const float*)d_in[1],  (const float*)d_in[3],
                          (const float*)d_in[5],  (const float*)d_in[7],
                          (const float*)d_in[9],  (const float*)d_in[11],
                          (const float*)d_in[13], (const float*)d_in[15]};
    const float* bv[8] = {(const float*)d_in[2],  (const float*)d_in[4],
                          (const float*)d_in[6],  (const float*)d_in[8],
                          (const float*)d_in[10], (const float*)d_in[12],
                          (const float*)d_in[14], (const float*)d_in[16]};
    const float* centers = (const float*)d_in[17];

    float* out    = (float*)d_out;
    float* recon  = out;
    float* emb    = out + (size_t)B_ROWS * D_IN;
    float* labels = emb + (size_t)B_ROWS * D_EMB;

    float *xh, *xl, *h0h, *h0l, *h1h, *h1l, *eh, *el, *wh, *wl, *ch, *cl, *c2;
    __nv_bfloat16 *ebh, *ebl, *wbh, *wbl, *d0h, *d0l, *d1h, *d1l;
    cudaGetSymbolAddress((void**)&xh, g_xh);   cudaGetSymbolAddress((void**)&xl, g_xl);
    cudaGetSymbolAddress((void**)&h0h, g_h0h); cudaGetSymbolAddress((void**)&h0l, g_h0l);
    cudaGetSymbolAddress((void**)&h1h, g_h1h); cudaGetSymbolAddress((void**)&h1l, g_h1l);
    cudaGetSymbolAddress((void**)&eh, g_eh);   cudaGetSymbolAddress((void**)&el, g_el);
    cudaGetSymbolAddress((void**)&wh, g_wh);   cudaGetSymbolAddress((void**)&wl, g_wl);
    cudaGetSymbolAddress((void**)&ch, g_ch);   cudaGetSymbolAddress((void**)&cl, g_cl);
    cudaGetSymbolAddress((void**)&c2, g_c2);
    cudaGetSymbolAddress((void**)&ebh, g_ebh); cudaGetSymbolAddress((void**)&ebl, g_ebl);
    cudaGetSymbolAddress((void**)&wbh, g_wbh); cudaGetSymbolAddress((void**)&wbl, g_wbl);
    cudaGetSymbolAddress((void**)&d0h, g_d0h); cudaGetSymbolAddress((void**)&d0l, g_d0l);
    cudaGetSymbolAddress((void**)&d1h, g_d1h); cudaGetSymbolAddress((void**)&d1l, g_d1l);

    const int fi[8] = {1024, 2048, 1024, 512, 256, 512, 1024, 2048};
    const int fo[8] = {2048, 1024, 512, 256, 512, 1024, 2048, 1024};
    size_t off[8], acc = 0, accd = 0;
    for (int i = 0; i < 4; i++) { off[i] = acc;  acc  += (size_t)fi[i] * fo[i]; }
    for (int i = 4; i < 8; i++) { off[i] = accd; accd += (size_t)fi[i] * fo[i]; }

    // ---- prep ----
    esplit_tf32<<<(B_ROWS * D_IN / 4 + 255) / 256, 256>>>(x, xh, xl, B_ROWS * D_IN / 4);
    esplit_tf32<<<(K_CENT * D_EMB / 4 + 255) / 256, 256>>>(centers, ch, cl, K_CENT * D_EMB / 4);
    c2_kernel<<<K_CENT / 8, 256>>>(centers, c2);
    for (int i = 0; i < 4; i++) {
        dim3 g(fo[i] / 32, fi[i] / 32), b(32, 8);
        wt_split_tf32<<<g, b>>>(W[i], wh + off[i], wl + off[i], fi[i], fo[i]);
    }
    for (int i = 4; i < 8; i++) {
        dim3 g(fo[i] / 32, fi[i] / 32), b(32, 8);
        wt_split_bf16<<<g, b>>>(W[i], wbh + off[i], wbl + off[i], fi[i], fo[i]);
    }

    // ---- encoder (tf32x3 + Neumaier) ----
    {
        dim3 g0(2048 / 64, B_ROWS / 128);
        gemm_tf32c<<<g0, 256, TF32C_SMEM>>>(xh, xl, wh + off[0], wl + off[0], bv[0],
                                            nullptr, h0h, h0l, B_ROWS, 2048, 1024, 1);
        dim3 g1(1024 / 64, B_ROWS / 128);
        gemm_tf32c<<<g1, 256, TF32C_SMEM>>>(h0h, h0l, wh + off[1], wl + off[1], bv[1],
                                            nullptr, h1h, h1l, B_ROWS, 1024, 2048, 1);
        dim3 g2(512 / 64, B_ROWS / 128);
        gemm_tf32c<<<g2, 256, TF32C_SMEM>>>(h1h, h1l, wh + off[2], wl + off[2], bv[2],
                                            nullptr, h0h, h0l, B_ROWS, 512, 1024, 1);
        dim3 g3(256 / 64, B_ROWS / 128);
        gemm_tf32c<<<g3, 256, TF32C_SMEM>>>(h0h, h0l, wh + off[3], wl + off[3], bv[3],
                                            emb, nullptr, nullptr, B_ROWS, 256, 512, 0);
    }
    emb_split<<<(B_ROWS * D_EMB / 2 + 255) / 256, 256>>>(emb, eh, el, ebh, ebl,
                                                         B_ROWS * D_EMB / 2);
    // ---- clustering ----
    {
        dim3 g(K_CENT / 64, B_ROWS / 128);
        gemm_tf32c<<<g, 256, TF32C_SMEM>>>(eh, el, ch, cl, nullptr,
                                           h1h, nullptr, nullptr, B_ROWS, K_CENT, D_EMB, 0);
    }
    argmin_labels<<<B_ROWS, 256>>>(emb, h1h, c2, labels);

    // ---- decoder (bf16x3) ----
    {
        dim3 g0(512 / 128, B_ROWS / 128);
        gemm_bf16<<<g0, 128, BF16_SMEM>>>(ebh, ebl, wbh + off[4], wbl + off[4], bv[4],
                                          nullptr, d0h, d0l, B_ROWS, 512, 256, 1);
        dim3 g1(1024 / 128, B_ROWS / 128);
        gemm_bf16<<<g1, 128, BF16_SMEM>>>(d0h, d0l, wbh + off[5], wbl + off[5], bv[5],
                                          nullptr, d1h, d1l, B_ROWS, 1024, 512, 1);
        dim3 g2(2048 / 128, B_ROWS / 128);
        gemm_bf16<<<g2, 128, BF16_SMEM>>>(d1h, d1l, wbh + off[6], wbl + off[6], bv[6],
                                          nullptr, d0h, d0l, B_ROWS, 2048, 1024, 1);
        dim3 g3(1024 / 128, B_ROWS / 128);
        gemm_bf16<<<g3, 128, BF16_SMEM>>>(d0h, d0l, wbh + off[7], wbl + off[7], bv[7],
                                          recon, nullptr, nullptr, B_ROWS, 1024, 2048, 0);
    }
}

// round 7
// speedup vs baseline: 2.2776x; 1.0890x over previous
#include <cuda_runtime.h>
#include <cuda_bf16.h>
#include <cstdint>
#include <cstddef>

#define B_ROWS 8192
#define D_IN   1024
#define D_EMB  256
#define K_CENT 1024
#define WSUM   4849664

// ---------------- device scratch ----------------
__device__ __align__(16) float g_h0[(size_t)B_ROWS * 2048];   // fp32 activations
__device__ __align__(16) float g_h1[(size_t)B_ROWS * 2048];   // fp32 activations / S
__device__ __align__(16) float g_wt[WSUM];                    // enc weights [N,K] fp32
__device__ __align__(16) __nv_bfloat16 g_ebh[(size_t)B_ROWS * D_EMB];
__device__ __align__(16) __nv_bfloat16 g_ebl[(size_t)B_ROWS * D_EMB];
__device__ __align__(16) __nv_bfloat16 g_wbh[WSUM];
__device__ __align__(16) __nv_bfloat16 g_wbl[WSUM];
__device__ __align__(16) __nv_bfloat16 g_d0h[(size_t)B_ROWS * 2048];
__device__ __align__(16) __nv_bfloat16 g_d0l[(size_t)B_ROWS * 2048];
__device__ __align__(16) __nv_bfloat16 g_d1h[(size_t)B_ROWS * 2048];
__device__ __align__(16) __nv_bfloat16 g_d1l[(size_t)B_ROWS * 2048];
__device__ float g_c2[K_CENT];

// ---------------- helpers ----------------
__device__ __forceinline__ uint32_t smem_u32(const void* p) {
    uint32_t a;
    asm("{ .reg .u64 t; cvta.to.shared.u64 t, %1; cvt.u32.u64 %0, t; }" : "=r"(a) : "l"(p));
    return a;
}
__device__ __forceinline__ float trunc_hi(float v) {
    return __uint_as_float(__float_as_uint(v) & 0xFFFFE000u);
}
__device__ __forceinline__ void split_bf16(float v, __nv_bfloat16& h, __nv_bfloat16& l) {
    h = __float2bfloat16(v);
    l = __float2bfloat16(v - __bfloat162float(h));
}
__device__ __forceinline__ void mma_tf32(float* d, const float* a, const float* b) {
    asm volatile(
        "mma.sync.aligned.m16n8k8.row.col.f32.tf32.tf32.f32 "
        "{%0,%1,%2,%3}, {%4,%5,%6,%7}, {%8,%9}, {%0,%1,%2,%3};"
        : "+f"(d[0]), "+f"(d[1]), "+f"(d[2]), "+f"(d[3])
        : "r"(__float_as_uint(a[0])), "r"(__float_as_uint(a[1])),
          "r"(__float_as_uint(a[2])), "r"(__float_as_uint(a[3])),
          "r"(__float_as_uint(b[0])), "r"(__float_as_uint(b[1])));
}
__device__ __forceinline__ void mma_bf16(float* d, const uint32_t* a, const uint32_t* b) {
    asm volatile(
        "mma.sync.aligned.m16n8k16.row.col.f32.bf16.bf16.f32 "
        "{%0,%1,%2,%3}, {%4,%5,%6,%7}, {%8,%9}, {%0,%1,%2,%3};"
        : "+f"(d[0]), "+f"(d[1]), "+f"(d[2]), "+f"(d[3])
        : "r"(a[0]), "r"(a[1]), "r"(a[2]), "r"(a[3]), "r"(b[0]), "r"(b[1]));
}
#define CP16(smaddr, gptr) \
    asm volatile("cp.async.cg.shared.global [%0], [%1], 16;" :: "r"(smaddr), "l"(gptr) : "memory")
#define CP_COMMIT() asm volatile("cp.async.commit_group;" ::: "memory")
#define CP_WAIT(n)  asm volatile("cp.async.wait_group %0;" :: "n"(n) : "memory")

// ===========================================================================
// tf32x3 GEMM, raw fp32 operands, in-register Dekker split, Neumaier chunks.
// C = A @ B^T (+bias)(relu?). A=[M,K] fp32, B=[N,K] fp32. Tile 128x64,
// 256 threads (8 warps, 32x32 warp tiles), BK=32, 3-stage cp.async.
// ===========================================================================
#define TF32R_SMEM (3 * 6912 * 4)   // A 128*36 + B 64*36 floats per stage

__global__ void __launch_bounds__(256)
gemm_tf32r(const float* __restrict__ A, const float* __restrict__ B,
           const float* __restrict__ bias, float* __restrict__ outF,
           int M, int N, int K, int doRelu)
{
    extern __shared__ float sm[];
    const int tid  = threadIdx.x;
    const int lane = tid & 31, wid = tid >> 5;
    const int g = lane >> 2, q = lane & 3;
    const int warpM = (wid & 3) * 32, warpN = (wid >> 2) * 32;
    const int brow = blockIdx.y * 128, bcol = blockIdx.x * 64;
    const int nch = K >> 5;
    const uint32_t smb = smem_u32(sm);

    float sum[2][4][4], comp[2][4][4];
    #pragma unroll
    for (int i = 0; i < 2; i++)
        #pragma unroll
        for (int j = 0; j < 4; j++)
            #pragma unroll
            for (int r = 0; r < 4; r++) { sum[i][j][r] = 0.f; comp[i][j][r] = 0.f; }

    auto issue = [&](int ch, int s) {
        int kt = ch << 5;
        uint32_t base = smb + (uint32_t)s * 6912u * 4u;
        #pragma unroll
        for (int it = 0; it < 4; it++) {             // A: 128 rows x 8 segs
            int id = it * 256 + tid;
            int row = id >> 3, seg = id & 7;
            CP16(base + (uint32_t)(row * 144 + seg * 16),
                 A + (size_t)(brow + row) * K + kt + seg * 4);
        }
        uint32_t baseB = base + 4608u * 4u;
        #pragma unroll
        for (int it = 0; it < 2; it++) {             // B: 64 rows x 8 segs
            int id = it * 256 + tid;
            int row = id >> 3, seg = id & 7;
            CP16(baseB + (uint32_t)(row * 144 + seg * 16),
                 B + (size_t)(bcol + row) * K + kt + seg * 4);
        }
        CP_COMMIT();
    };

    issue(0, 0);
    if (nch > 1) issue(1, 1); else CP_COMMIT();
    if (nch > 2) issue(2, 2); else CP_COMMIT();

    for (int c = 0; c < nch; c++) {
        int s = c % 3;
        CP_WAIT(2);
        __syncthreads();

        const float* sA = sm + s * 6912;
        const float* sB = sA + 4608;

        float acc[2][4][4];
        #pragma unroll
        for (int i = 0; i < 2; i++)
            #pragma unroll
            for (int j = 0; j < 4; j++)
                #pragma unroll
                for (int r = 0; r < 4; r++) acc[i][j][r] = 0.f;

        #pragma unroll
        for (int kb = 0; kb < 32; kb += 8) {
            float ah[2][4], al[2][4], bh[4][2], bl[4][2];
            #pragma unroll
            for (int i = 0; i < 2; i++) {
                int r0 = (warpM + i * 16 + g) * 36 + kb + q;
                float r00 = sA[r0],       r01 = sA[r0 + 288];
                float r02 = sA[r0 + 4],   r03 = sA[r0 + 292];
                ah[i][0] = trunc_hi(r00); al[i][0] = r00 - ah[i][0];
                ah[i][1] = trunc_hi(r01); al[i][1] = r01 - ah[i][1];
                ah[i][2] = trunc_hi(r02); al[i][2] = r02 - ah[i][2];
                ah[i][3] = trunc_hi(r03); al[i][3] = r03 - ah[i][3];
            }
            #pragma unroll
            for (int j = 0; j < 4; j++) {
                int rn = (warpN + j * 8 + g) * 36 + kb + q;
                float r0v = sB[rn], r1v = sB[rn + 4];
                bh[j][0] = trunc_hi(r0v); bl[j][0] = r0v - bh[j][0];
                bh[j][1] = trunc_hi(r1v); bl[j][1] = r1v - bh[j][1];
            }
            #pragma unroll
            for (int i = 0; i < 2; i++)
                #pragma unroll
                for (int j = 0; j < 4; j++) {
                    mma_tf32(acc[i][j], ah[i], bh[j]);
                    mma_tf32(acc[i][j], ah[i], bl[j]);
                    mma_tf32(acc[i][j], al[i], bh[j]);
                }
        }

        // Neumaier fold
        #pragma unroll
        for (int i = 0; i < 2; i++)
            #pragma unroll
            for (int j = 0; j < 4; j++)
                #pragma unroll
                for (int r = 0; r < 4; r++) {
                    float v = acc[i][j][r];
                    float so = sum[i][j][r];
                    float t = so + v;
                    float e = (fabsf(so) >= fabsf(v)) ? ((so - t) + v) : ((v - t) + so);
                    comp[i][j][r] += e;
                    sum[i][j][r] = t;
                }

        __syncthreads();
        if (c + 3 < nch) issue(c + 3, s); else CP_COMMIT();
    }

    #pragma unroll
    for (int i = 0; i < 2; i++) {
        int r0 = brow + warpM + i * 16 + g;
        #pragma unroll
        for (int j = 0; j < 4; j++) {
            int col = bcol + warpN + j * 8 + 2 * q;
            float b0 = 0.f, b1 = 0.f;
            if (bias) { b0 = __ldg(bias + col); b1 = __ldg(bias + col + 1); }
            float v00 = (sum[i][j][0] + comp[i][j][0]) + b0;
            float v01 = (sum[i][j][1] + comp[i][j][1]) + b1;
            float v10 = (sum[i][j][2] + comp[i][j][2]) + b0;
            float v11 = (sum[i][j][3] + comp[i][j][3]) + b1;
            if (doRelu) {
                v00 = fmaxf(v00, 0.f); v01 = fmaxf(v01, 0.f);
                v10 = fmaxf(v10, 0.f); v11 = fmaxf(v11, 0.f);
            }
            size_t o0 = (size_t)r0 * N + col, o1 = o0 + 8 * (size_t)N;
            *reinterpret_cast<float2*>(outF + o0) = make_float2(v00, v01);
            *reinterpret_cast<float2*>(outF + o1) = make_float2(v10, v11);
        }
    }
}

// ===========================================================================
// bf16 3-product GEMM, 256 threads (8 warps, 32x64 warp tiles): decoder.
// ===========================================================================
#define BF16_SMEM (12 * 5120 * 2)

__global__ void __launch_bounds__(256)
gemm_bf16(const __nv_bfloat16* __restrict__ pAh, const __nv_bfloat16* __restrict__ pAl,
          const __nv_bfloat16* __restrict__ pBh, const __nv_bfloat16* __restrict__ pBl,
          const float* __restrict__ bias,
          float* __restrict__ outF,
          __nv_bfloat16* __restrict__ outH, __nv_bfloat16* __restrict__ outL,
          int M, int N, int K, int doRelu)
{
    extern __shared__ __nv_bfloat16 smb16[];
    const int tid  = threadIdx.x;
    const int lane = tid & 31, wid = tid >> 5;
    const int g = lane >> 2, q = lane & 3;
    const int warpM = (wid & 3) * 32, warpN = (wid >> 2) * 64;
    const int brow = blockIdx.y * 128, bcol = blockIdx.x * 128;
    const int nch = K >> 5;
    const uint32_t smb = smem_u32(smb16);

    float acc[2][8][4];
    #pragma unroll
    for (int i = 0; i < 2; i++)
        #pragma unroll
        for (int j = 0; j < 8; j++)
            #pragma unroll
            for (int r = 0; r < 4; r++) acc[i][j][r] = 0.0f;

    const __nv_bfloat16* gp[4] = {pAh, pAl, pBh, pBl};
    const int rb[4] = {brow, brow, bcol, bcol};

    auto issue = [&](int ch, int s) {
        int kt = ch << 5;
        #pragma unroll
        for (int a = 0; a < 4; a++) {
            uint32_t base = smb + (uint32_t)(s * 4 + a) * 5120u * 2u;
            #pragma unroll
            for (int it = 0; it < 2; it++) {
                int id = it * 256 + tid;
                int row = id >> 2, seg = id & 3;
                const __nv_bfloat16* src = gp[a] + (size_t)(rb[a] + row) * K + kt + seg * 8;
                CP16(base + (uint32_t)(row * 80 + seg * 16), src);
            }
        }
        CP_COMMIT();
    };

    issue(0, 0);
    if (nch > 1) issue(1, 1); else CP_COMMIT();
    if (nch > 2) issue(2, 2); else CP_COMMIT();

    for (int c = 0; c < nch; c++) {
        int s = c % 3;
        CP_WAIT(2);
        __syncthreads();

        const __nv_bfloat16* sAh = smb16 + (s * 4 + 0) * 5120;
        const __nv_bfloat16* sAl = smb16 + (s * 4 + 1) * 5120;
        const __nv_bfloat16* sBh = smb16 + (s * 4 + 2) * 5120;
        const __nv_bfloat16* sBl = smb16 + (s * 4 + 3) * 5120;

        #pragma unroll
        for (int kb = 0; kb < 32; kb += 16) {
            uint32_t ah[2][4], al[2][4], bh[8][2], bl[8][2];
            #pragma unroll
            for (int i = 0; i < 2; i++) {
                int e0 = (warpM + i * 16 + g) * 40 + kb + 2 * q;
                ah[i][0] = *reinterpret_cast<const uint32_t*>(sAh + e0);
                ah[i][1] = *reinterpret_cast<const uint32_t*>(sAh + e0 + 320);
                ah[i][2] = *reinterpret_cast<const uint32_t*>(sAh + e0 + 8);
                ah[i][3] = *reinterpret_cast<const uint32_t*>(sAh + e0 + 328);
                al[i][0] = *reinterpret_cast<const uint32_t*>(sAl + e0);
                al[i][1] = *reinterpret_cast<const uint32_t*>(sAl + e0 + 320);
                al[i][2] = *reinterpret_cast<const uint32_t*>(sAl + e0 + 8);
                al[i][3] = *reinterpret_cast<const uint32_t*>(sAl + e0 + 328);
            }
            #pragma unroll
            for (int j = 0; j < 8; j++) {
                int en = (warpN + j * 8 + g) * 40 + kb + 2 * q;
                bh[j][0] = *reinterpret_cast<const uint32_t*>(sBh + en);
                bh[j][1] = *reinterpret_cast<const uint32_t*>(sBh + en + 8);
                bl[j][0] = *reinterpret_cast<const uint32_t*>(sBl + en);
                bl[j][1] = *reinterpret_cast<const uint32_t*>(sBl + en + 8);
            }
            #pragma unroll
            for (int i = 0; i < 2; i++)
                #pragma unroll
                for (int j = 0; j < 8; j++) {
                    mma_bf16(acc[i][j], ah[i], bh[j]);
                    mma_bf16(acc[i][j], ah[i], bl[j]);
                    mma_bf16(acc[i][j], al[i], bh[j]);
                }
        }
        __syncthreads();
        if (c + 3 < nch) issue(c + 3, s); else CP_COMMIT();
    }

    #pragma unroll
    for (int i = 0; i < 2; i++) {
        int r0 = brow + warpM + i * 16 + g;
        #pragma unroll
        for (int j = 0; j < 8; j++) {
            int col = bcol + warpN + j * 8 + 2 * q;
            float b0 = 0.f, b1 = 0.f;
            if (bias) { b0 = __ldg(bias + col); b1 = __ldg(bias + col + 1); }
            float v00 = acc[i][j][0] + b0, v01 = acc[i][j][1] + b1;
            float v10 = acc[i][j][2] + b0, v11 = acc[i][j][3] + b1;
            if (doRelu) {
                v00 = fmaxf(v00, 0.f); v01 = fmaxf(v01, 0.f);
                v10 = fmaxf(v10, 0.f); v11 = fmaxf(v11, 0.f);
            }
            size_t o0 = (size_t)r0 * N + col, o1 = o0 + 8 * (size_t)N;
            if (outF) {
                *reinterpret_cast<float2*>(outF + o0) = make_float2(v00, v01);
                *reinterpret_cast<float2*>(outF + o1) = make_float2(v10, v11);
            }
            if (outH) {
                __nv_bfloat16 h[4], l[4];
                split_bf16(v00, h[0], l[0]); split_bf16(v01, h[1], l[1]);
                split_bf16(v10, h[2], l[2]); split_bf16(v11, h[3], l[3]);
                *reinterpret_cast<__nv_bfloat162*>(outH + o0) = __nv_bfloat162(h[0], h[1]);
                *reinterpret_cast<__nv_bfloat162*>(outH + o1) = __nv_bfloat162(h[2], h[3]);
                *reinterpret_cast<__nv_bfloat162*>(outL + o0) = __nv_bfloat162(l[0], l[1]);
                *reinterpret_cast<__nv_bfloat162*>(outL + o1) = __nv_bfloat162(l[2], l[3]);
            }
        }
    }
}

// ---------------- prep kernels ----------------
__global__ void wt_trans(const float* __restrict__ W, float* __restrict__ out,
                         int Kd, int N)
{   // W [Kd,N] -> out [N,Kd] fp32
    __shared__ float t[32][33];
    int bx = blockIdx.x * 32, by = blockIdx.y * 32;
    for (int i = threadIdx.y; i < 32; i += 8)
        t[i][threadIdx.x] = W[(size_t)(by + i) * N + bx + threadIdx.x];
    __syncthreads();
    for (int i = threadIdx.y; i < 32; i += 8)
        out[(size_t)(bx + i) * Kd + by + threadIdx.x] = t[threadIdx.x][i];
}

__global__ void wt_split_bf16(const float* __restrict__ W, __nv_bfloat16* __restrict__ hi,
                              __nv_bfloat16* __restrict__ lo, int Kd, int N)
{
    __shared__ float t[32][33];
    int bx = blockIdx.x * 32, by = blockIdx.y * 32;
    for (int i = threadIdx.y; i < 32; i += 8)
        t[i][threadIdx.x] = W[(size_t)(by + i) * N + bx + threadIdx.x];
    __syncthreads();
    for (int i = threadIdx.y; i < 32; i += 8) {
        float v = t[threadIdx.x][i];
        __nv_bfloat16 h, l;
        split_bf16(v, h, l);
        size_t o = (size_t)(bx + i) * Kd + by + threadIdx.x;
        hi[o] = h; lo[o] = l;
    }
}

__global__ void emb_split_bf16(const float* __restrict__ a,
                               __nv_bfloat16* __restrict__ bh,
                               __nv_bfloat16* __restrict__ bl, int n2)
{
    int i = blockIdx.x * blockDim.x + threadIdx.x;
    if (i >= n2) return;
    float2 v = reinterpret_cast<const float2*>(a)[i];
    __nv_bfloat16 bhx, blx, bhy, bly;
    split_bf16(v.x, bhx, blx); split_bf16(v.y, bhy, bly);
    reinterpret_cast<__nv_bfloat162*>(bh)[i] = __nv_bfloat162(bhx, bhy);
    reinterpret_cast<__nv_bfloat162*>(bl)[i] = __nv_bfloat162(blx, bly);
}

__global__ void c2_kernel(const float* __restrict__ c, float* __restrict__ c2)
{
    int k = blockIdx.x * 8 + (threadIdx.x >> 5);
    int lane = threadIdx.x & 31;
    float s = 0.0f;
    for (int d = lane; d < D_EMB; d += 32) {
        float v = c[(size_t)k * D_EMB + d];
        s = fmaf(v, v, s);
    }
    #pragma unroll
    for (int o = 16; o; o >>= 1) s += __shfl_xor_sync(0xFFFFFFFFu, s, o);
    if (lane == 0) c2[k] = s;
}

__global__ void argmin_labels(const float* __restrict__ emb, const float* __restrict__ S,
                              const float* __restrict__ c2, float* __restrict__ labels)
{
    const int row = blockIdx.x, tid = threadIdx.x;
    __shared__ float red[256];
    float v = emb[(size_t)row * D_EMB + tid];
    red[tid] = v * v;
    __syncthreads();
    #pragma unroll
    for (int s = 128; s > 0; s >>= 1) {
        if (tid < s) red[tid] += red[tid + s];
        __syncthreads();
    }
    const float e2 = red[0];
    __syncthreads();
    float best = 3.402823466e38f;
    int bi = 0;
    for (int k = tid; k < K_CENT; k += 256) {
        float d = fmaxf(e2 + c2[k] - 2.0f * S[(size_t)row * K_CENT + k], 0.0f);
        if (d < best) { best = d; bi = k; }
    }
    __shared__ float sv[256];
    __shared__ int si[256];
    sv[tid] = best; si[tid] = bi;
    __syncthreads();
    #pragma unroll
    for (int s = 128; s > 0; s >>= 1) {
        if (tid < s) {
            float v2 = sv[tid + s]; int i2 = si[tid + s];
            if (v2 < sv[tid] || (v2 == sv[tid] && i2 < si[tid])) { sv[tid] = v2; si[tid] = i2; }
        }
        __syncthreads();
    }
    const int win = si[0];
    for (int k = tid; k < K_CENT; k += 256)
        labels[(size_t)row * K_CENT + k] = (k == win) ? 1.0f : 0.0f;
}

// ---------------- host launcher ----------------
extern "C" void kernel_launch(void* const* d_in, const int* in_sizes, int n_in,
                              void* d_out, int out_size)
{
    (void)in_sizes; (void)n_in; (void)out_size;

    cudaFuncSetAttribute(gemm_tf32r, cudaFuncAttributeMaxDynamicSharedMemorySize, TF32R_SMEM);
    cudaFuncSetAttribute(gemm_bf16,  cudaFuncAttributeMaxDynamicSharedMemorySize, BF16_SMEM);

    const float* x = (const float*)d_in[0];
    const float* W[8]  = {(const float*)d_in[1],  (const float*)d_in[3],
                          (const float*)d_in[5],  (const float*)d_in[7],
                          (const float*)d_in[9],  (const float*)d_in[11],
                          (const float*)d_in[13], (const float*)d_in[15]};
    const float* bv[8] = {(const float*)d_in[2],  (const float*)d_in[4],
                          (const float*)d_in[6],  (const float*)d_in[8],
                          (const float*)d_in[10], (const float*)d_in[12],
                          (const float*)d_in[14], (const float*)d_in[16]};
    const float* centers = (const float*)d_in[17];

    float* out    = (float*)d_out;
    float* recon  = out;
    float* emb    = out + (size_t)B_ROWS * D_IN;
    float* labels = emb + (size_t)B_ROWS * D_EMB;

    float *h0, *h1, *wt, *c2;
    __nv_bfloat16 *ebh, *ebl, *wbh, *wbl, *d0h, *d0l, *d1h, *d1l;
    cudaGetSymbolAddress((void**)&h0, g_h0);
    cudaGetSymbolAddress((void**)&h1, g_h1);
    cudaGetSymbolAddress((void**)&wt, g_wt);
    cudaGetSymbolAddress((void**)&c2, g_c2);
    cudaGetSymbolAddress((void**)&ebh, g_ebh); cudaGetSymbolAddress((void**)&ebl, g_ebl);
    cudaGetSymbolAddress((void**)&wbh, g_wbh); cudaGetSymbolAddress((void**)&wbl, g_wbl);
    cudaGetSymbolAddress((void**)&d0h, g_d0h); cudaGetSymbolAddress((void**)&d0l, g_d0l);
    cudaGetSymbolAddress((void**)&d1h, g_d1h); cudaGetSymbolAddress((void**)&d1l, g_d1l);

    const int fi[8] = {1024, 2048, 1024, 512, 256, 512, 1024, 2048};
    const int fo[8] = {2048, 1024, 512, 256, 512, 1024, 2048, 1024};
    size_t off[8], acc = 0, accd = 0;
    for (int i = 0; i < 4; i++) { off[i] = acc;  acc  += (size_t)fi[i] * fo[i]; }
    for (int i = 4; i < 8; i++) { off[i] = accd; accd += (size_t)fi[i] * fo[i]; }

    // ---- prep ----
    c2_kernel<<<K_CENT / 8, 256>>>(centers, c2);
    for (int i = 0; i < 4; i++) {
        dim3 g(fo[i] / 32, fi[i] / 32), b(32, 8);
        wt_trans<<<g, b>>>(W[i], wt + off[i], fi[i], fo[i]);
    }
    for (int i = 4; i < 8; i++) {
        dim3 g(fo[i] / 32, fi[i] / 32), b(32, 8);
        wt_split_bf16<<<g, b>>>(W[i], wbh + off[i], wbl + off[i], fi[i], fo[i]);
    }

    // ---- encoder (tf32x3, raw fp32 operands, in-register split) ----
    {
        dim3 g0(2048 / 64, B_ROWS / 128);
        gemm_tf32r<<<g0, 256, TF32R_SMEM>>>(x,  wt + off[0], bv[0], h0, B_ROWS, 2048, 1024, 1);
        dim3 g1(1024 / 64, B_ROWS / 128);
        gemm_tf32r<<<g1, 256, TF32R_SMEM>>>(h0, wt + off[1], bv[1], h1, B_ROWS, 1024, 2048, 1);
        dim3 g2(512 / 64, B_ROWS / 128);
        gemm_tf32r<<<g2, 256, TF32R_SMEM>>>(h1, wt + off[2], bv[2], h0, B_ROWS, 512, 1024, 1);
        dim3 g3(256 / 64, B_ROWS / 128);
        gemm_tf32r<<<g3, 256, TF32R_SMEM>>>(h0, wt + off[3], bv[3], emb, B_ROWS, 256, 512, 0);
    }
    emb_split_bf16<<<(B_ROWS * D_EMB / 2 + 255) / 256, 256>>>(emb, ebh, ebl,
                                                              B_ROWS * D_EMB / 2);
    // ---- clustering: S = emb @ centers^T (centers already [N,K]) ----
    {
        dim3 g(K_CENT / 64, B_ROWS / 128);
        gemm_tf32r<<<g, 256, TF32R_SMEM>>>(emb, centers, nullptr, h1, B_ROWS, K_CENT, D_EMB, 0);
    }
    argmin_labels<<<B_ROWS, 256>>>(emb, h1, c2, labels);

    // ---- decoder (bf16x3, 8 warps) ----
    {
        dim3 g0(512 / 128, B_ROWS / 128);
        gemm_bf16<<<g0, 256, BF16_SMEM>>>(ebh, ebl, wbh + off[4], wbl + off[4], bv[4],
                                          nullptr, d0h, d0l, B_ROWS, 512, 256, 1);
        dim3 g1(1024 / 128, B_ROWS / 128);
        gemm_bf16<<<g1, 256, BF16_SMEM>>>(d0h, d0l, wbh + off[5], wbl + off[5], bv[5],
                                          nullptr, d1h, d1l, B_ROWS, 1024, 512, 1);
        dim3 g2(2048 / 128, B_ROWS / 128);
        gemm_bf16<<<g2, 256, BF16_SMEM>>>(d1h, d1l, wbh + off[6], wbl + off[6], bv[6],
                                          nullptr, d0h, d0l, B_ROWS, 2048, 1024, 1);
        dim3 g3(1024 / 128, B_ROWS / 128);
        gemm_bf16<<<g3, 256, BF16_SMEM>>>(d0h, d0l, wbh + off[7], wbl + off[7], bv[7],
                                          recon, nullptr, nullptr, B_ROWS, 1024, 2048, 0);
    }
}

// round 8
// speedup vs baseline: 2.5212x; 1.1070x over previous
#include <cuda_runtime.h>
#include <cuda_bf16.h>
#include <cstdint>
#include <cstddef>

#define B_ROWS 8192
#define D_IN   1024
#define D_EMB  256
#define K_CENT 1024
#define WSUM   4849664

// ---------------- device scratch ----------------
__device__ __align__(16) float g_h0[(size_t)B_ROWS * 2048];
__device__ __align__(16) float g_h1[(size_t)B_ROWS * 2048];
__device__ __align__(16) float g_wt[WSUM];
__device__ __align__(16) __nv_bfloat16 g_ebh[(size_t)B_ROWS * D_EMB];
__device__ __align__(16) __nv_bfloat16 g_ebl[(size_t)B_ROWS * D_EMB];
__device__ __align__(16) __nv_bfloat16 g_wbh[WSUM];
__device__ __align__(16) __nv_bfloat16 g_wbl[WSUM];
__device__ __align__(16) __nv_bfloat16 g_d0h[(size_t)B_ROWS * 2048];
__device__ __align__(16) __nv_bfloat16 g_d0l[(size_t)B_ROWS * 2048];
__device__ __align__(16) __nv_bfloat16 g_d1h[(size_t)B_ROWS * 2048];
__device__ __align__(16) __nv_bfloat16 g_d1l[(size_t)B_ROWS * 2048];
__device__ float g_c2[K_CENT];

// ---------------- helpers ----------------
__device__ __forceinline__ uint32_t smem_u32(const void* p) {
    uint32_t a;
    asm("{ .reg .u64 t; cvta.to.shared.u64 t, %1; cvt.u32.u64 %0, t; }" : "=r"(a) : "l"(p));
    return a;
}
__device__ __forceinline__ float trunc_hi(float v) {
    return __uint_as_float(__float_as_uint(v) & 0xFFFFE000u);
}
__device__ __forceinline__ void split_bf16(float v, __nv_bfloat16& h, __nv_bfloat16& l) {
    h = __float2bfloat16(v);
    l = __float2bfloat16(v - __bfloat162float(h));
}
__device__ __forceinline__ void mma_tf32(float* d, const float* a, const float* b) {
    asm volatile(
        "mma.sync.aligned.m16n8k8.row.col.f32.tf32.tf32.f32 "
        "{%0,%1,%2,%3}, {%4,%5,%6,%7}, {%8,%9}, {%0,%1,%2,%3};"
        : "+f"(d[0]), "+f"(d[1]), "+f"(d[2]), "+f"(d[3])
        : "r"(__float_as_uint(a[0])), "r"(__float_as_uint(a[1])),
          "r"(__float_as_uint(a[2])), "r"(__float_as_uint(a[3])),
          "r"(__float_as_uint(b[0])), "r"(__float_as_uint(b[1])));
}
__device__ __forceinline__ void mma_bf16(float* d, const uint32_t* a, const uint32_t* b) {
    asm volatile(
        "mma.sync.aligned.m16n8k16.row.col.f32.bf16.bf16.f32 "
        "{%0,%1,%2,%3}, {%4,%5,%6,%7}, {%8,%9}, {%0,%1,%2,%3};"
        : "+f"(d[0]), "+f"(d[1]), "+f"(d[2]), "+f"(d[3])
        : "r"(a[0]), "r"(a[1]), "r"(a[2]), "r"(a[3]), "r"(b[0]), "r"(b[1]));
}
#define CP16(smaddr, gptr) \
    asm volatile("cp.async.cg.shared.global [%0], [%1], 16;" :: "r"(smaddr), "l"(gptr) : "memory")
#define CP_COMMIT() asm volatile("cp.async.commit_group;" ::: "memory")
#define CP_WAIT(n)  asm volatile("cp.async.wait_group %0;" :: "n"(n) : "memory")

// ===========================================================================
// tf32x3 GEMM, raw fp32 operands, in-register split, branchless Kahan chunks.
// Tile 128x64, 256 thr (8 warps, 32x32 warp tiles), BK=32, 3-stage cp.async.
// Forced 2 CTAs/SM.
// ===========================================================================
#define TF32R_SMEM (3 * 6912 * 4)

__global__ void __launch_bounds__(256, 2)
gemm_tf32r(const float* __restrict__ A, const float* __restrict__ B,
           const float* __restrict__ bias, float* __restrict__ outF,
           int M, int N, int K, int doRelu)
{
    extern __shared__ float sm[];
    const int tid  = threadIdx.x;
    const int lane = tid & 31, wid = tid >> 5;
    const int g = lane >> 2, q = lane & 3;
    const int warpM = (wid & 3) * 32, warpN = (wid >> 2) * 32;
    const int brow = blockIdx.y * 128, bcol = blockIdx.x * 64;
    const int nch = K >> 5;
    const uint32_t smb = smem_u32(sm);

    float sum[2][4][4], comp[2][4][4];
    #pragma unroll
    for (int i = 0; i < 2; i++)
        #pragma unroll
        for (int j = 0; j < 4; j++)
            #pragma unroll
            for (int r = 0; r < 4; r++) { sum[i][j][r] = 0.f; comp[i][j][r] = 0.f; }

    auto issue = [&](int ch, int s) {
        int kt = ch << 5;
        uint32_t base = smb + (uint32_t)s * 6912u * 4u;
        #pragma unroll
        for (int it = 0; it < 4; it++) {
            int id = it * 256 + tid;
            int row = id >> 3, seg = id & 7;
            CP16(base + (uint32_t)(row * 144 + seg * 16),
                 A + (size_t)(brow + row) * K + kt + seg * 4);
        }
        uint32_t baseB = base + 4608u * 4u;
        #pragma unroll
        for (int it = 0; it < 2; it++) {
            int id = it * 256 + tid;
            int row = id >> 3, seg = id & 7;
            CP16(baseB + (uint32_t)(row * 144 + seg * 16),
                 B + (size_t)(bcol + row) * K + kt + seg * 4);
        }
        CP_COMMIT();
    };

    issue(0, 0);
    if (nch > 1) issue(1, 1); else CP_COMMIT();
    if (nch > 2) issue(2, 2); else CP_COMMIT();

    for (int c = 0; c < nch; c++) {
        int s = c % 3;
        CP_WAIT(2);
        __syncthreads();

        const float* sA = sm + s * 6912;
        const float* sB = sA + 4608;

        float acc[2][4][4];
        #pragma unroll
        for (int i = 0; i < 2; i++)
            #pragma unroll
            for (int j = 0; j < 4; j++)
                #pragma unroll
                for (int r = 0; r < 4; r++) acc[i][j][r] = 0.f;

        #pragma unroll
        for (int kb = 0; kb < 32; kb += 8) {
            float ah[2][4], al[2][4];
            #pragma unroll
            for (int i = 0; i < 2; i++) {
                int r0 = (warpM + i * 16 + g) * 36 + kb + q;
                float r00 = sA[r0],     r01 = sA[r0 + 288];
                float r02 = sA[r0 + 4], r03 = sA[r0 + 292];
                ah[i][0] = trunc_hi(r00); al[i][0] = r00 - ah[i][0];
                ah[i][1] = trunc_hi(r01); al[i][1] = r01 - ah[i][1];
                ah[i][2] = trunc_hi(r02); al[i][2] = r02 - ah[i][2];
                ah[i][3] = trunc_hi(r03); al[i][3] = r03 - ah[i][3];
            }
            #pragma unroll
            for (int j = 0; j < 4; j++) {
                int rn = (warpN + j * 8 + g) * 36 + kb + q;
                float b0 = sB[rn], b1 = sB[rn + 4];
                float bh[2], bl[2];
                bh[0] = trunc_hi(b0); bl[0] = b0 - bh[0];
                bh[1] = trunc_hi(b1); bl[1] = b1 - bh[1];
                #pragma unroll
                for (int i = 0; i < 2; i++) {
                    mma_tf32(acc[i][j], ah[i], bh);
                    mma_tf32(acc[i][j], ah[i], bl);
                    mma_tf32(acc[i][j], al[i], bh);
                }
            }
        }

        // branchless Kahan fold
        #pragma unroll
        for (int i = 0; i < 2; i++)
            #pragma unroll
            for (int j = 0; j < 4; j++)
                #pragma unroll
                for (int r = 0; r < 4; r++) {
                    float v = acc[i][j][r];
                    float so = sum[i][j][r];
                    float t = so + v;
                    comp[i][j][r] += (so - t) + v;
                    sum[i][j][r] = t;
                }

        __syncthreads();
        if (c + 3 < nch) issue(c + 3, s); else CP_COMMIT();
    }

    #pragma unroll
    for (int i = 0; i < 2; i++) {
        int r0 = brow + warpM + i * 16 + g;
        #pragma unroll
        for (int j = 0; j < 4; j++) {
            int col = bcol + warpN + j * 8 + 2 * q;
            float b0 = 0.f, b1 = 0.f;
            if (bias) { b0 = __ldg(bias + col); b1 = __ldg(bias + col + 1); }
            float v00 = (sum[i][j][0] + comp[i][j][0]) + b0;
            float v01 = (sum[i][j][1] + comp[i][j][1]) + b1;
            float v10 = (sum[i][j][2] + comp[i][j][2]) + b0;
            float v11 = (sum[i][j][3] + comp[i][j][3]) + b1;
            if (doRelu) {
                v00 = fmaxf(v00, 0.f); v01 = fmaxf(v01, 0.f);
                v10 = fmaxf(v10, 0.f); v11 = fmaxf(v11, 0.f);
            }
            size_t o0 = (size_t)r0 * N + col, o1 = o0 + 8 * (size_t)N;
            *reinterpret_cast<float2*>(outF + o0) = make_float2(v00, v01);
            *reinterpret_cast<float2*>(outF + o1) = make_float2(v10, v11);
        }
    }
}

// ===========================================================================
// bf16 3-product GEMM: 128x64 CTA tile, 8 warps (32x32), 2 CTAs/SM.
// Stage: Ah[128*40] Al[128*40] Bh[64*40] Bl[64*40] bf16 = 30720 B.
// ===========================================================================
#define BF16_SMEM (3 * 30720)

__global__ void __launch_bounds__(256, 2)
gemm_bf16(const __nv_bfloat16* __restrict__ pAh, const __nv_bfloat16* __restrict__ pAl,
          const __nv_bfloat16* __restrict__ pBh, const __nv_bfloat16* __restrict__ pBl,
          const float* __restrict__ bias,
          float* __restrict__ outF,
          __nv_bfloat16* __restrict__ outH, __nv_bfloat16* __restrict__ outL,
          int M, int N, int K, int doRelu)
{
    extern __shared__ __nv_bfloat16 smb16[];
    const int tid  = threadIdx.x;
    const int lane = tid & 31, wid = tid >> 5;
    const int g = lane >> 2, q = lane & 3;
    const int warpM = (wid & 3) * 32, warpN = (wid >> 2) * 32;
    const int brow = blockIdx.y * 128, bcol = blockIdx.x * 64;
    const int nch = K >> 5;
    const uint32_t smb = smem_u32(smb16);

    float acc[2][4][4];
    #pragma unroll
    for (int i = 0; i < 2; i++)
        #pragma unroll
        for (int j = 0; j < 4; j++)
            #pragma unroll
            for (int r = 0; r < 4; r++) acc[i][j][r] = 0.0f;

    auto issue = [&](int ch, int s) {
        int kt = ch << 5;
        uint32_t sbase = smb + (uint32_t)s * 30720u;
        const __nv_bfloat16* gpA[2] = {pAh, pAl};
        const __nv_bfloat16* gpB[2] = {pBh, pBl};
        #pragma unroll
        for (int a = 0; a < 2; a++) {
            uint32_t base = sbase + (uint32_t)a * 10240u;
            #pragma unroll
            for (int it = 0; it < 2; it++) {
                int id = it * 256 + tid;
                int row = id >> 2, seg = id & 3;
                CP16(base + (uint32_t)(row * 80 + seg * 16),
                     gpA[a] + (size_t)(brow + row) * K + kt + seg * 8);
            }
        }
        #pragma unroll
        for (int a = 0; a < 2; a++) {
            uint32_t base = sbase + 20480u + (uint32_t)a * 5120u;
            int row = tid >> 2, seg = tid & 3;
            CP16(base + (uint32_t)(row * 80 + seg * 16),
                 gpB[a] + (size_t)(bcol + row) * K + kt + seg * 8);
        }
        CP_COMMIT();
    };

    issue(0, 0);
    if (nch > 1) issue(1, 1); else CP_COMMIT();
    if (nch > 2) issue(2, 2); else CP_COMMIT();

    for (int c = 0; c < nch; c++) {
        int s = c % 3;
        CP_WAIT(2);
        __syncthreads();

        const __nv_bfloat16* sAh = smb16 + s * 15360;
        const __nv_bfloat16* sAl = sAh + 5120;
        const __nv_bfloat16* sBh = sAh + 10240;
        const __nv_bfloat16* sBl = sAh + 12800;

        #pragma unroll
        for (int kb = 0; kb < 32; kb += 16) {
            uint32_t ah[2][4], al[2][4];
            #pragma unroll
            for (int i = 0; i < 2; i++) {
                int e0 = (warpM + i * 16 + g) * 40 + kb + 2 * q;
                ah[i][0] = *reinterpret_cast<const uint32_t*>(sAh + e0);
                ah[i][1] = *reinterpret_cast<const uint32_t*>(sAh + e0 + 320);
                ah[i][2] = *reinterpret_cast<const uint32_t*>(sAh + e0 + 8);
                ah[i][3] = *reinterpret_cast<const uint32_t*>(sAh + e0 + 328);
                al[i][0] = *reinterpret_cast<const uint32_t*>(sAl + e0);
                al[i][1] = *reinterpret_cast<const uint32_t*>(sAl + e0 + 320);
                al[i][2] = *reinterpret_cast<const uint32_t*>(sAl + e0 + 8);
                al[i][3] = *reinterpret_cast<const uint32_t*>(sAl + e0 + 328);
            }
            #pragma unroll
            for (int j = 0; j < 4; j++) {
                int en = (warpN + j * 8 + g) * 40 + kb + 2 * q;
                uint32_t bh[2], bl[2];
                bh[0] = *reinterpret_cast<const uint32_t*>(sBh + en);
                bh[1] = *reinterpret_cast<const uint32_t*>(sBh + en + 8);
                bl[0] = *reinterpret_cast<const uint32_t*>(sBl + en);
                bl[1] = *reinterpret_cast<const uint32_t*>(sBl + en + 8);
                #pragma unroll
                for (int i = 0; i < 2; i++) {
                    mma_bf16(acc[i][j], ah[i], bh);
                    mma_bf16(acc[i][j], ah[i], bl);
                    mma_bf16(acc[i][j], al[i], bh);
                }
            }
        }
        __syncthreads();
        if (c + 3 < nch) issue(c + 3, s); else CP_COMMIT();
    }

    #pragma unroll
    for (int i = 0; i < 2; i++) {
        int r0 = brow + warpM + i * 16 + g;
        #pragma unroll
        for (int j = 0; j < 4; j++) {
            int col = bcol + warpN + j * 8 + 2 * q;
            float b0 = 0.f, b1 = 0.f;
            if (bias) { b0 = __ldg(bias + col); b1 = __ldg(bias + col + 1); }
            float v00 = acc[i][j][0] + b0, v01 = acc[i][j][1] + b1;
            float v10 = acc[i][j][2] + b0, v11 = acc[i][j][3] + b1;
            if (doRelu) {
                v00 = fmaxf(v00, 0.f); v01 = fmaxf(v01, 0.f);
                v10 = fmaxf(v10, 0.f); v11 = fmaxf(v11, 0.f);
            }
            size_t o0 = (size_t)r0 * N + col, o1 = o0 + 8 * (size_t)N;
            if (outF) {
                *reinterpret_cast<float2*>(outF + o0) = make_float2(v00, v01);
                *reinterpret_cast<float2*>(outF + o1) = make_float2(v10, v11);
            }
            if (outH) {
                __nv_bfloat16 h[4], l[4];
                split_bf16(v00, h[0], l[0]); split_bf16(v01, h[1], l[1]);
                split_bf16(v10, h[2], l[2]); split_bf16(v11, h[3], l[3]);
                *reinterpret_cast<__nv_bfloat162*>(outH + o0) = __nv_bfloat162(h[0], h[1]);
                *reinterpret_cast<__nv_bfloat162*>(outH + o1) = __nv_bfloat162(h[2], h[3]);
                *reinterpret_cast<__nv_bfloat162*>(outL + o0) = __nv_bfloat162(l[0], l[1]);
                *reinterpret_cast<__nv_bfloat162*>(outL + o1) = __nv_bfloat162(l[2], l[3]);
            }
        }
    }
}

// ---------------- prep kernels ----------------
__global__ void wt_trans(const float* __restrict__ W, float* __restrict__ out,
                         int Kd, int N)
{
    __shared__ float t[32][33];
    int bx = blockIdx.x * 32, by = blockIdx.y * 32;
    for (int i = threadIdx.y; i < 32; i += 8)
        t[i][threadIdx.x] = W[(size_t)(by + i) * N + bx + threadIdx.x];
    __syncthreads();
    for (int i = threadIdx.y; i < 32; i += 8)
        out[(size_t)(bx + i) * Kd + by + threadIdx.x] = t[threadIdx.x][i];
}

__global__ void wt_split_bf16(const float* __restrict__ W, __nv_bfloat16* __restrict__ hi,
                              __nv_bfloat16* __restrict__ lo, int Kd, int N)
{
    __shared__ float t[32][33];
    int bx = blockIdx.x * 32, by = blockIdx.y * 32;
    for (int i = threadIdx.y; i < 32; i += 8)
        t[i][threadIdx.x] = W[(size_t)(by + i) * N + bx + threadIdx.x];
    __syncthreads();
    for (int i = threadIdx.y; i < 32; i += 8) {
        float v = t[threadIdx.x][i];
        __nv_bfloat16 h, l;
        split_bf16(v, h, l);
        size_t o = (size_t)(bx + i) * Kd + by + threadIdx.x;
        hi[o] = h; lo[o] = l;
    }
}

__global__ void emb_split_bf16(const float* __restrict__ a,
                               __nv_bfloat16* __restrict__ bh,
                               __nv_bfloat16* __restrict__ bl, int n2)
{
    int i = blockIdx.x * blockDim.x + threadIdx.x;
    if (i >= n2) return;
    float2 v = reinterpret_cast<const float2*>(a)[i];
    __nv_bfloat16 bhx, blx, bhy, bly;
    split_bf16(v.x, bhx, blx); split_bf16(v.y, bhy, bly);
    reinterpret_cast<__nv_bfloat162*>(bh)[i] = __nv_bfloat162(bhx, bhy);
    reinterpret_cast<__nv_bfloat162*>(bl)[i] = __nv_bfloat162(blx, bly);
}

__global__ void c2_kernel(const float* __restrict__ c, float* __restrict__ c2)
{
    int k = blockIdx.x * 8 + (threadIdx.x >> 5);
    int lane = threadIdx.x & 31;
    float s = 0.0f;
    for (int d = lane; d < D_EMB; d += 32) {
        float v = c[(size_t)k * D_EMB + d];
        s = fmaf(v, v, s);
    }
    #pragma unroll
    for (int o = 16; o; o >>= 1) s += __shfl_xor_sync(0xFFFFFFFFu, s, o);
    if (lane == 0) c2[k] = s;
}

__global__ void argmin_labels(const float* __restrict__ emb, const float* __restrict__ S,
                              const float* __restrict__ c2, float* __restrict__ labels)
{
    const int row = blockIdx.x, tid = threadIdx.x;
    __shared__ float red[256];
    float v = emb[(size_t)row * D_EMB + tid];
    red[tid] = v * v;
    __syncthreads();
    #pragma unroll
    for (int s = 128; s > 0; s >>= 1) {
        if (tid < s) red[tid] += red[tid + s];
        __syncthreads();
    }
    const float e2 = red[0];
    __syncthreads();
    float best = 3.402823466e38f;
    int bi = 0;
    for (int k = tid; k < K_CENT; k += 256) {
        float d = fmaxf(e2 + c2[k] - 2.0f * S[(size_t)row * K_CENT + k], 0.0f);
        if (d < best) { best = d; bi = k; }
    }
    __shared__ float sv[256];
    __shared__ int si[256];
    sv[tid] = best; si[tid] = bi;
    __syncthreads();
    #pragma unroll
    for (int s = 128; s > 0; s >>= 1) {
        if (tid < s) {
            float v2 = sv[tid + s]; int i2 = si[tid + s];
            if (v2 < sv[tid] || (v2 == sv[tid] && i2 < si[tid])) { sv[tid] = v2; si[tid] = i2; }
        }
        __syncthreads();
    }
    const int win = si[0];
    for (int k = tid; k < K_CENT; k += 256)
        labels[(size_t)row * K_CENT + k] = (k == win) ? 1.0f : 0.0f;
}

// ---------------- host launcher ----------------
extern "C" void kernel_launch(void* const* d_in, const int* in_sizes, int n_in,
                              void* d_out, int out_size)
{
    (void)in_sizes; (void)n_in; (void)out_size;

    cudaFuncSetAttribute(gemm_tf32r, cudaFuncAttributeMaxDynamicSharedMemorySize, TF32R_SMEM);
    cudaFuncSetAttribute(gemm_bf16,  cudaFuncAttributeMaxDynamicSharedMemorySize, BF16_SMEM);

    const float* x = (const float*)d_in[0];
    const float* W[8]  = {(const float*)d_in[1],  (const float*)d_in[3],
                          (const float*)d_in[5],  (const float*)d_in[7],
                          (const float*)d_in[9],  (const float*)d_in[11],
                          (const float*)d_in[13], (const float*)d_in[15]};
    const float* bv[8] = {(const float*)d_in[2],  (const float*)d_in[4],
                          (const float*)d_in[6],  (const float*)d_in[8],
                          (const float*)d_in[10], (const float*)d_in[12],
                          (const float*)d_in[14], (const float*)d_in[16]};
    const float* centers = (const float*)d_in[17];

    float* out    = (float*)d_out;
    float* recon  = out;
    float* emb    = out + (size_t)B_ROWS * D_IN;
    float* labels = emb + (size_t)B_ROWS * D_EMB;

    float *h0, *h1, *wt, *c2;
    __nv_bfloat16 *ebh, *ebl, *wbh, *wbl, *d0h, *d0l, *d1h, *d1l;
    cudaGetSymbolAddress((void**)&h0, g_h0);
    cudaGetSymbolAddress((void**)&h1, g_h1);
    cudaGetSymbolAddress((void**)&wt, g_wt);
    cudaGetSymbolAddress((void**)&c2, g_c2);
    cudaGetSymbolAddress((void**)&ebh, g_ebh); cudaGetSymbolAddress((void**)&ebl, g_ebl);
    cudaGetSymbolAddress((void**)&wbh, g_wbh); cudaGetSymbolAddress((void**)&wbl, g_wbl);
    cudaGetSymbolAddress((void**)&d0h, g_d0h); cudaGetSymbolAddress((void**)&d0l, g_d0l);
    cudaGetSymbolAddress((void**)&d1h, g_d1h); cudaGetSymbolAddress((void**)&d1l, g_d1l);

    const int fi[8] = {1024, 2048, 1024, 512, 256, 512, 1024, 2048};
    const int fo[8] = {2048, 1024, 512, 256, 512, 1024, 2048, 1024};
    size_t off[8], acc = 0, accd = 0;
    for (int i = 0; i < 4; i++) { off[i] = acc;  acc  += (size_t)fi[i] * fo[i]; }
    for (int i = 4; i < 8; i++) { off[i] = accd; accd += (size_t)fi[i] * fo[i]; }

    auto wtp = [&](int i) {
        dim3 g(fo[i] / 32, fi[i] / 32), b(32, 8);
        wt_trans<<<g, b>>>(W[i], wt + off[i], fi[i], fo[i]);
    };

    // Launch order puts the two biggest encoder GEMMs at positions 4-5 so the
    // ncu capture window (skip ~4-5) lands on a GEMM, not a prep kernel.
    c2_kernel<<<K_CENT / 8, 256>>>(centers, c2);                           // 1
    wtp(0);                                                                // 2
    wtp(1);                                                                // 3
    {
        dim3 g0(2048 / 64, B_ROWS / 128);                                  // 4
        gemm_tf32r<<<g0, 256, TF32R_SMEM>>>(x,  wt + off[0], bv[0], h0, B_ROWS, 2048, 1024, 1);
        dim3 g1(1024 / 64, B_ROWS / 128);                                  // 5
        gemm_tf32r<<<g1, 256, TF32R_SMEM>>>(h0, wt + off[1], bv[1], h1, B_ROWS, 1024, 2048, 1);
    }
    wtp(2);                                                                // 6
    {
        dim3 g2(512 / 64, B_ROWS / 128);                                   // 7
        gemm_tf32r<<<g2, 256, TF32R_SMEM>>>(h1, wt + off[2], bv[2], h0, B_ROWS, 512, 1024, 1);
    }
    wtp(3);                                                                // 8
    {
        dim3 g3(256 / 64, B_ROWS / 128);                                   // 9
        gemm_tf32r<<<g3, 256, TF32R_SMEM>>>(h0, wt + off[3], bv[3], emb, B_ROWS, 256, 512, 0);
    }

    emb_split_bf16<<<(B_ROWS * D_EMB / 2 + 255) / 256, 256>>>(emb, ebh, ebl,
                                                              B_ROWS * D_EMB / 2);
    // clustering: S = emb @ centers^T (centers already [N,K] row-major)
    {
        dim3 g(K_CENT / 64, B_ROWS / 128);
        gemm_tf32r<<<g, 256, TF32R_SMEM>>>(emb, centers, nullptr, h1, B_ROWS, K_CENT, D_EMB, 0);
    }
    argmin_labels<<<B_ROWS, 256>>>(emb, h1, c2, labels);

    // decoder weight prep
    for (int i = 4; i < 8; i++) {
        dim3 g(fo[i] / 32, fi[i] / 32), b(32, 8);
        wt_split_bf16<<<g, b>>>(W[i], wbh + off[i], wbl + off[i], fi[i], fo[i]);
    }
    // decoder (bf16x3, 128x64 tiles, 2 CTAs/SM)
    {
        dim3 g0(512 / 64, B_ROWS / 128);
        gemm_bf16<<<g0, 256, BF16_SMEM>>>(ebh, ebl, wbh + off[4], wbl + off[4], bv[4],
                                          nullptr, d0h, d0l, B_ROWS, 512, 256, 1);
        dim3 g1(1024 / 64, B_ROWS / 128);
        gemm_bf16<<<g1, 256, BF16_SMEM>>>(d0h, d0l, wbh + off[5], wbl + off[5], bv[5],
                                          nullptr, d1h, d1l, B_ROWS, 1024, 512, 1);
        dim3 g2(2048 / 64, B_ROWS / 128);
        gemm_bf16<<<g2, 256, BF16_SMEM>>>(d1h, d1l, wbh + off[6], wbl + off[6], bv[6],
                                          nullptr, d0h, d0l, B_ROWS, 2048, 1024, 1);
        dim3 g3(1024 / 64, B_ROWS / 128);
        gemm_bf16<<<g3, 256, BF16_SMEM>>>(d0h, d0l, wbh + off[7], wbl + off[7], bv[7],
                                          recon, nullptr, nullptr, B_ROWS, 1024, 2048, 0);
    }
}

// round 9
// speedup vs baseline: 3.4589x; 1.3720x over previous
#include <cuda_runtime.h>
#include <cuda_fp16.h>
#include <cstdint>
#include <cstddef>

#define B_ROWS 8192
#define D_IN   1024
#define D_EMB  256
#define K_CENT 1024
#define WSUM   4849664

// ---------------- device scratch ----------------
__device__ __align__(16) __half g_xh[(size_t)B_ROWS * D_IN];
__device__ __align__(16) __half g_xl[(size_t)B_ROWS * D_IN];
__device__ __align__(16) __half g_h0h[(size_t)B_ROWS * 2048];
__device__ __align__(16) __half g_h0l[(size_t)B_ROWS * 2048];
__device__ __align__(16) __half g_h1h[(size_t)B_ROWS * 2048];
__device__ __align__(16) __half g_h1l[(size_t)B_ROWS * 2048];
__device__ __align__(16) __half g_eh[(size_t)B_ROWS * D_EMB];
__device__ __align__(16) __half g_el[(size_t)B_ROWS * D_EMB];
__device__ __align__(16) __half g_weh[WSUM];   // enc weights [N,K] fp16 hi
__device__ __align__(16) __half g_wel[WSUM];   // enc weights [N,K] fp16 lo
__device__ __align__(16) __half g_wd[WSUM];    // dec weights [N,K] fp16 single
__device__ __align__(16) __half g_ch[K_CENT * D_EMB];
__device__ __align__(16) __half g_cl[K_CENT * D_EMB];
__device__ __align__(16) float  g_S[(size_t)B_ROWS * K_CENT];
__device__ float g_c2[K_CENT];

// ---------------- helpers ----------------
__device__ __forceinline__ uint32_t smem_u32(const void* p) {
    uint32_t a;
    asm("{ .reg .u64 t; cvta.to.shared.u64 t, %1; cvt.u32.u64 %0, t; }" : "=r"(a) : "l"(p));
    return a;
}
__device__ __forceinline__ void split_fp16(float v, __half& h, __half& l) {
    h = __float2half_rn(v);
    l = __float2half_rn(v - __half2float(h));
}
__device__ __forceinline__ void mma_fp16(float* d, const uint32_t* a, const uint32_t* b) {
    asm volatile(
        "mma.sync.aligned.m16n8k16.row.col.f32.f16.f16.f32 "
        "{%0,%1,%2,%3}, {%4,%5,%6,%7}, {%8,%9}, {%0,%1,%2,%3};"
        : "+f"(d[0]), "+f"(d[1]), "+f"(d[2]), "+f"(d[3])
        : "r"(a[0]), "r"(a[1]), "r"(a[2]), "r"(a[3]), "r"(b[0]), "r"(b[1]));
}
#define CP16(smaddr, gptr) \
    asm volatile("cp.async.cg.shared.global [%0], [%1], 16;" :: "r"(smaddr), "l"(gptr) : "memory")
#define CP_COMMIT() asm volatile("cp.async.commit_group;" ::: "memory")
#define CP_WAIT(n)  asm volatile("cp.async.wait_group %0;" :: "n"(n) : "memory")

#define U32AT(p) (*reinterpret_cast<const uint32_t*>(p))

// ===========================================================================
// Encoder GEMM: fp16x3 (hh+hl+lh), both operands as fp16 (h,l) pairs.
// C = A @ B^T (+bias)(relu?). Tile 128x64, 8 warps (32x32), BK=32, 3 stages.
// Kahan fold every 2 chunks. 2 CTAs/SM.
// Stage: Ah[128*40] Al[128*40] Bh[64*40] Bl[64*40] halves = 30720 B.
// ===========================================================================
#define FP16E_SMEM (3 * 30720)

__global__ void __launch_bounds__(256, 2)
gemm_fp16e(const __half* __restrict__ Ah, const __half* __restrict__ Al,
           const __half* __restrict__ Bh, const __half* __restrict__ Bl,
           const float* __restrict__ bias,
           float* __restrict__ outF, __half* __restrict__ outH, __half* __restrict__ outL,
           int M, int N, int K, int doRelu)
{
    extern __shared__ __half smh[];
    const int tid  = threadIdx.x;
    const int lane = tid & 31, wid = tid >> 5;
    const int g = lane >> 2, q = lane & 3;
    const int warpM = (wid & 3) * 32, warpN = (wid >> 2) * 32;
    const int brow = blockIdx.y * 128, bcol = blockIdx.x * 64;
    const int nch = K >> 5;
    const uint32_t smb = smem_u32(smh);

    float sum[2][4][4], comp[2][4][4], acc[2][4][4];
    #pragma unroll
    for (int i = 0; i < 2; i++)
        #pragma unroll
        for (int j = 0; j < 4; j++)
            #pragma unroll
            for (int r = 0; r < 4; r++) { sum[i][j][r] = 0.f; comp[i][j][r] = 0.f; acc[i][j][r] = 0.f; }

    const __half* gpA[2] = {Ah, Al};
    const __half* gpB[2] = {Bh, Bl};

    auto issue = [&](int ch, int s) {
        int kt = ch << 5;
        uint32_t sbase = smb + (uint32_t)s * 30720u;
        #pragma unroll
        for (int a = 0; a < 2; a++) {
            uint32_t base = sbase + (uint32_t)a * 10240u;
            #pragma unroll
            for (int it = 0; it < 2; it++) {
                int id = it * 256 + tid;
                int row = id >> 2, seg = id & 3;
                CP16(base + (uint32_t)(row * 80 + seg * 16),
                     gpA[a] + (size_t)(brow + row) * K + kt + seg * 8);
            }
        }
        #pragma unroll
        for (int a = 0; a < 2; a++) {
            uint32_t base = sbase + 20480u + (uint32_t)a * 5120u;
            int row = tid >> 2, seg = tid & 3;
            CP16(base + (uint32_t)(row * 80 + seg * 16),
                 gpB[a] + (size_t)(bcol + row) * K + kt + seg * 8);
        }
        CP_COMMIT();
    };

    issue(0, 0);
    if (nch > 1) issue(1, 1); else CP_COMMIT();
    if (nch > 2) issue(2, 2); else CP_COMMIT();

    for (int c = 0; c < nch; c++) {
        int s = c % 3;
        CP_WAIT(2);
        __syncthreads();

        const __half* sAh = smh + s * 15360;
        const __half* sAl = sAh + 5120;
        const __half* sBh = sAh + 10240;
        const __half* sBl = sAh + 12800;

        #pragma unroll
        for (int kb = 0; kb < 32; kb += 16) {
            uint32_t ah[2][4], al[2][4];
            #pragma unroll
            for (int i = 0; i < 2; i++) {
                int e0 = (warpM + i * 16 + g) * 40 + kb + 2 * q;
                ah[i][0] = U32AT(sAh + e0);       ah[i][1] = U32AT(sAh + e0 + 320);
                ah[i][2] = U32AT(sAh + e0 + 8);   ah[i][3] = U32AT(sAh + e0 + 328);
                al[i][0] = U32AT(sAl + e0);       al[i][1] = U32AT(sAl + e0 + 320);
                al[i][2] = U32AT(sAl + e0 + 8);   al[i][3] = U32AT(sAl + e0 + 328);
            }
            #pragma unroll
            for (int j = 0; j < 4; j++) {
                int en = (warpN + j * 8 + g) * 40 + kb + 2 * q;
                uint32_t bh[2], bl[2];
                bh[0] = U32AT(sBh + en);  bh[1] = U32AT(sBh + en + 8);
                bl[0] = U32AT(sBl + en);  bl[1] = U32AT(sBl + en + 8);
                #pragma unroll
                for (int i = 0; i < 2; i++) {
                    mma_fp16(acc[i][j], ah[i], bh);
                    mma_fp16(acc[i][j], ah[i], bl);
                    mma_fp16(acc[i][j], al[i], bh);
                }
            }
        }

        if ((c & 1) || c == nch - 1) {
            // branchless Kahan fold, then reset acc
            #pragma unroll
            for (int i = 0; i < 2; i++)
                #pragma unroll
                for (int j = 0; j < 4; j++)
                    #pragma unroll
                    for (int r = 0; r < 4; r++) {
                        float v = acc[i][j][r];
                        float so = sum[i][j][r];
                        float t = so + v;
                        comp[i][j][r] += (so - t) + v;
                        sum[i][j][r] = t;
                        acc[i][j][r] = 0.f;
                    }
        }

        __syncthreads();
        if (c + 3 < nch) issue(c + 3, s); else CP_COMMIT();
    }

    #pragma unroll
    for (int i = 0; i < 2; i++) {
        int r0 = brow + warpM + i * 16 + g;
        #pragma unroll
        for (int j = 0; j < 4; j++) {
            int col = bcol + warpN + j * 8 + 2 * q;
            float b0 = 0.f, b1 = 0.f;
            if (bias) { b0 = __ldg(bias + col); b1 = __ldg(bias + col + 1); }
            float v00 = (sum[i][j][0] + comp[i][j][0]) + b0;
            float v01 = (sum[i][j][1] + comp[i][j][1]) + b1;
            float v10 = (sum[i][j][2] + comp[i][j][2]) + b0;
            float v11 = (sum[i][j][3] + comp[i][j][3]) + b1;
            if (doRelu) {
                v00 = fmaxf(v00, 0.f); v01 = fmaxf(v01, 0.f);
                v10 = fmaxf(v10, 0.f); v11 = fmaxf(v11, 0.f);
            }
            size_t o0 = (size_t)r0 * N + col, o1 = o0 + 8 * (size_t)N;
            if (outF) {
                *reinterpret_cast<float2*>(outF + o0) = make_float2(v00, v01);
                *reinterpret_cast<float2*>(outF + o1) = make_float2(v10, v11);
            }
            if (outH) {
                __half h[4], l[4];
                split_fp16(v00, h[0], l[0]); split_fp16(v01, h[1], l[1]);
                split_fp16(v10, h[2], l[2]); split_fp16(v11, h[3], l[3]);
                *reinterpret_cast<__half2*>(outH + o0) = __halves2half2(h[0], h[1]);
                *reinterpret_cast<__half2*>(outH + o1) = __halves2half2(h[2], h[3]);
                *reinterpret_cast<__half2*>(outL + o0) = __halves2half2(l[0], l[1]);
                *reinterpret_cast<__half2*>(outL + o1) = __halves2half2(l[2], l[3]);
            }
        }
    }
}

// ===========================================================================
// Decoder GEMM: fp16x2 asymmetric — A as (h,l) pair, W single fp16.
// Stage: Ah[128*40] Al[128*40] W[64*40] halves = 25600 B. 2 CTAs/SM.
// ===========================================================================
#define FP16D_SMEM (3 * 25600)

__global__ void __launch_bounds__(256, 2)
gemm_fp16d(const __half* __restrict__ Ah, const __half* __restrict__ Al,
           const __half* __restrict__ W,
           const float* __restrict__ bias,
           float* __restrict__ outF, __half* __restrict__ outH, __half* __restrict__ outL,
           int M, int N, int K, int doRelu)
{
    extern __shared__ __half smh[];
    const int tid  = threadIdx.x;
    const int lane = tid & 31, wid = tid >> 5;
    const int g = lane >> 2, q = lane & 3;
    const int warpM = (wid & 3) * 32, warpN = (wid >> 2) * 32;
    const int brow = blockIdx.y * 128, bcol = blockIdx.x * 64;
    const int nch = K >> 5;
    const uint32_t smb = smem_u32(smh);

    float acc[2][4][4];
    #pragma unroll
    for (int i = 0; i < 2; i++)
        #pragma unroll
        for (int j = 0; j < 4; j++)
            #pragma unroll
            for (int r = 0; r < 4; r++) acc[i][j][r] = 0.f;

    const __half* gpA[2] = {Ah, Al};

    auto issue = [&](int ch, int s) {
        int kt = ch << 5;
        uint32_t sbase = smb + (uint32_t)s * 25600u;
        #pragma unroll
        for (int a = 0; a < 2; a++) {
            uint32_t base = sbase + (uint32_t)a * 10240u;
            #pragma unroll
            for (int it = 0; it < 2; it++) {
                int id = it * 256 + tid;
                int row = id >> 2, seg = id & 3;
                CP16(base + (uint32_t)(row * 80 + seg * 16),
                     gpA[a] + (size_t)(brow + row) * K + kt + seg * 8);
            }
        }
        {
            uint32_t base = sbase + 20480u;
            int row = tid >> 2, seg = tid & 3;
            CP16(base + (uint32_t)(row * 80 + seg * 16),
                 W + (size_t)(bcol + row) * K + kt + seg * 8);
        }
        CP_COMMIT();
    };

    issue(0, 0);
    if (nch > 1) issue(1, 1); else CP_COMMIT();
    if (nch > 2) issue(2, 2); else CP_COMMIT();

    for (int c = 0; c < nch; c++) {
        int s = c % 3;
        CP_WAIT(2);
        __syncthreads();

        const __half* sAh = smh + s * 12800;
        const __half* sAl = sAh + 5120;
        const __half* sW  = sAh + 10240;

        #pragma unroll
        for (int kb = 0; kb < 32; kb += 16) {
            uint32_t ah[2][4], al[2][4];
            #pragma unroll
            for (int i = 0; i < 2; i++) {
                int e0 = (warpM + i * 16 + g) * 40 + kb + 2 * q;
                ah[i][0] = U32AT(sAh + e0);       ah[i][1] = U32AT(sAh + e0 + 320);
                ah[i][2] = U32AT(sAh + e0 + 8);   ah[i][3] = U32AT(sAh + e0 + 328);
                al[i][0] = U32AT(sAl + e0);       al[i][1] = U32AT(sAl + e0 + 320);
                al[i][2] = U32AT(sAl + e0 + 8);   al[i][3] = U32AT(sAl + e0 + 328);
            }
            #pragma unroll
            for (int j = 0; j < 4; j++) {
                int en = (warpN + j * 8 + g) * 40 + kb + 2 * q;
                uint32_t bw[2];
                bw[0] = U32AT(sW + en);  bw[1] = U32AT(sW + en + 8);
                #pragma unroll
                for (int i = 0; i < 2; i++) {
                    mma_fp16(acc[i][j], ah[i], bw);
                    mma_fp16(acc[i][j], al[i], bw);
                }
            }
        }
        __syncthreads();
        if (c + 3 < nch) issue(c + 3, s); else CP_COMMIT();
    }

    #pragma unroll
    for (int i = 0; i < 2; i++) {
        int r0 = brow + warpM + i * 16 + g;
        #pragma unroll
        for (int j = 0; j < 4; j++) {
            int col = bcol + warpN + j * 8 + 2 * q;
            float b0 = 0.f, b1 = 0.f;
            if (bias) { b0 = __ldg(bias + col); b1 = __ldg(bias + col + 1); }
            float v00 = acc[i][j][0] + b0, v01 = acc[i][j][1] + b1;
            float v10 = acc[i][j][2] + b0, v11 = acc[i][j][3] + b1;
            if (doRelu) {
                v00 = fmaxf(v00, 0.f); v01 = fmaxf(v01, 0.f);
                v10 = fmaxf(v10, 0.f); v11 = fmaxf(v11, 0.f);
            }
            size_t o0 = (size_t)r0 * N + col, o1 = o0 + 8 * (size_t)N;
            if (outF) {
                *reinterpret_cast<float2*>(outF + o0) = make_float2(v00, v01);
                *reinterpret_cast<float2*>(outF + o1) = make_float2(v10, v11);
            }
            if (outH) {
                __half h[4], l[4];
                split_fp16(v00, h[0], l[0]); split_fp16(v01, h[1], l[1]);
                split_fp16(v10, h[2], l[2]); split_fp16(v11, h[3], l[3]);
                *reinterpret_cast<__half2*>(outH + o0) = __halves2half2(h[0], h[1]);
                *reinterpret_cast<__half2*>(outH + o1) = __halves2half2(h[2], h[3]);
                *reinterpret_cast<__half2*>(outL + o0) = __halves2half2(l[0], l[1]);
                *reinterpret_cast<__half2*>(outL + o1) = __halves2half2(l[2], l[3]);
            }
        }
    }
}

// ---------------- prep kernels ----------------
__global__ void vec_split_fp16(const float* __restrict__ a,
                               __half* __restrict__ hi, __half* __restrict__ lo, int n2)
{
    int i = blockIdx.x * blockDim.x + threadIdx.x;
    if (i >= n2) return;
    float2 v = reinterpret_cast<const float2*>(a)[i];
    __half hx, lx, hy, ly;
    split_fp16(v.x, hx, lx); split_fp16(v.y, hy, ly);
    reinterpret_cast<__half2*>(hi)[i] = __halves2half2(hx, hy);
    reinterpret_cast<__half2*>(lo)[i] = __halves2half2(lx, ly);
}

__global__ void wt_split_fp16(const float* __restrict__ W, __half* __restrict__ hi,
                              __half* __restrict__ lo, int Kd, int N)
{   // W [Kd,N] -> hi/lo [N,Kd]
    __shared__ float t[32][33];
    int bx = blockIdx.x * 32, by = blockIdx.y * 32;
    for (int i = threadIdx.y; i < 32; i += 8)
        t[i][threadIdx.x] = W[(size_t)(by + i) * N + bx + threadIdx.x];
    __syncthreads();
    for (int i = threadIdx.y; i < 32; i += 8) {
        float v = t[threadIdx.x][i];
        __half h, l;
        split_fp16(v, h, l);
        size_t o = (size_t)(bx + i) * Kd + by + threadIdx.x;
        hi[o] = h; lo[o] = l;
    }
}

__global__ void wt_single_fp16(const float* __restrict__ W, __half* __restrict__ out,
                               int Kd, int N)
{   // W [Kd,N] -> out [N,Kd] single fp16
    __shared__ float t[32][33];
    int bx = blockIdx.x * 32, by = blockIdx.y * 32;
    for (int i = threadIdx.y; i < 32; i += 8)
        t[i][threadIdx.x] = W[(size_t)(by + i) * N + bx + threadIdx.x];
    __syncthreads();
    for (int i = threadIdx.y; i < 32; i += 8)
        out[(size_t)(bx + i) * Kd + by + threadIdx.x] = __float2half_rn(t[threadIdx.x][i]);
}

__global__ void c2_kernel(const float* __restrict__ c, float* __restrict__ c2)
{
    int k = blockIdx.x * 8 + (threadIdx.x >> 5);
    int lane = threadIdx.x & 31;
    float s = 0.0f;
    for (int d = lane; d < D_EMB; d += 32) {
        float v = c[(size_t)k * D_EMB + d];
        s = fmaf(v, v, s);
    }
    #pragma unroll
    for (int o = 16; o; o >>= 1) s += __shfl_xor_sync(0xFFFFFFFFu, s, o);
    if (lane == 0) c2[k] = s;
}

__global__ void argmin_labels(const float* __restrict__ emb, const float* __restrict__ S,
                              const float* __restrict__ c2, float* __restrict__ labels)
{
    const int row = blockIdx.x, tid = threadIdx.x;
    __shared__ float red[256];
    float v = emb[(size_t)row * D_EMB + tid];
    red[tid] = v * v;
    __syncthreads();
    #pragma unroll
    for (int s = 128; s > 0; s >>= 1) {
        if (tid < s) red[tid] += red[tid + s];
        __syncthreads();
    }
    const float e2 = red[0];
    __syncthreads();
    float best = 3.402823466e38f;
    int bi = 0;
    for (int k = tid; k < K_CENT; k += 256) {
        float d = fmaxf(e2 + c2[k] - 2.0f * S[(size_t)row * K_CENT + k], 0.0f);
        if (d < best) { best = d; bi = k; }
    }
    __shared__ float sv[256];
    __shared__ int si[256];
    sv[tid] = best; si[tid] = bi;
    __syncthreads();
    #pragma unroll
    for (int s = 128; s > 0; s >>= 1) {
        if (tid < s) {
            float v2 = sv[tid + s]; int i2 = si[tid + s];
            if (v2 < sv[tid] || (v2 == sv[tid] && i2 < si[tid])) { sv[tid] = v2; si[tid] = i2; }
        }
        __syncthreads();
    }
    const int win = si[0];
    for (int k = tid; k < K_CENT; k += 256)
        labels[(size_t)row * K_CENT + k] = (k == win) ? 1.0f : 0.0f;
}

// ---------------- host launcher ----------------
extern "C" void kernel_launch(void* const* d_in, const int* in_sizes, int n_in,
                              void* d_out, int out_size)
{
    (void)in_sizes; (void)n_in; (void)out_size;

    cudaFuncSetAttribute(gemm_fp16e, cudaFuncAttributeMaxDynamicSharedMemorySize, FP16E_SMEM);
    cudaFuncSetAttribute(gemm_fp16d, cudaFuncAttributeMaxDynamicSharedMemorySize, FP16D_SMEM);

    const float* x = (const float*)d_in[0];
    const float* W[8]  = {(const float*)d_in[1],  (const float*)d_in[3],
                          (const float*)d_in[5],  (const float*)d_in[7],
                          (const float*)d_in[9],  (const float*)d_in[11],
                          (const float*)d_in[13], (const float*)d_in[15]};
    const float* bv[8] = {(const float*)d_in[2],  (const float*)d_in[4],
                          (const float*)d_in[6],  (const float*)d_in[8],
                          (const float*)d_in[10], (const float*)d_in[12],
                          (const float*)d_in[14], (const float*)d_in[16]};
    const float* centers = (const float*)d_in[17];

    float* out    = (float*)d_out;
    float* recon  = out;
    float* emb    = out + (size_t)B_ROWS * D_IN;
    float* labels = emb + (size_t)B_ROWS * D_EMB;

    __half *xh, *xl, *h0h, *h0l, *h1h, *h1l, *eh, *el, *weh, *wel, *wd, *ch, *cl;
    float *S, *c2;
    cudaGetSymbolAddress((void**)&xh, g_xh);   cudaGetSymbolAddress((void**)&xl, g_xl);
    cudaGetSymbolAddress((void**)&h0h, g_h0h); cudaGetSymbolAddress((void**)&h0l, g_h0l);
    cudaGetSymbolAddress((void**)&h1h, g_h1h); cudaGetSymbolAddress((void**)&h1l, g_h1l);
    cudaGetSymbolAddress((void**)&eh, g_eh);   cudaGetSymbolAddress((void**)&el, g_el);
    cudaGetSymbolAddress((void**)&weh, g_weh); cudaGetSymbolAddress((void**)&wel, g_wel);
    cudaGetSymbolAddress((void**)&wd, g_wd);
    cudaGetSymbolAddress((void**)&ch, g_ch);   cudaGetSymbolAddress((void**)&cl, g_cl);
    cudaGetSymbolAddress((void**)&S, g_S);     cudaGetSymbolAddress((void**)&c2, g_c2);

    const int fi[8] = {1024, 2048, 1024, 512, 256, 512, 1024, 2048};
    const int fo[8] = {2048, 1024, 512, 256, 512, 1024, 2048, 1024};
    size_t off[8], acc = 0, accd = 0;
    for (int i = 0; i < 4; i++) { off[i] = acc;  acc  += (size_t)fi[i] * fo[i]; }
    for (int i = 4; i < 8; i++) { off[i] = accd; accd += (size_t)fi[i] * fo[i]; }

    auto wenc = [&](int i) {
        dim3 g(fo[i] / 32, fi[i] / 32), b(32, 8);
        wt_split_fp16<<<g, b>>>(W[i], weh + off[i], wel + off[i], fi[i], fo[i]);
    };

    // prep + encoder (big GEMMs early for ncu window)
    c2_kernel<<<K_CENT / 8, 256>>>(centers, c2);                               // 1
    vec_split_fp16<<<(B_ROWS * D_IN / 2 + 255) / 256, 256>>>(x, xh, xl,
                                                             B_ROWS * D_IN / 2); // 2
    wenc(0);                                                                   // 3
    {
        dim3 g0(2048 / 64, B_ROWS / 128);                                      // 4
        gemm_fp16e<<<g0, 256, FP16E_SMEM>>>(xh, xl, weh + off[0], wel + off[0], bv[0],
                                            nullptr, h0h, h0l, B_ROWS, 2048, 1024, 1);
    }
    wenc(1);                                                                   // 5
    {
        dim3 g1(1024 / 64, B_ROWS / 128);                                      // 6
        gemm_fp16e<<<g1, 256, FP16E_SMEM>>>(h0h, h0l, weh + off[1], wel + off[1], bv[1],
                                            nullptr, h1h, h1l, B_ROWS, 1024, 2048, 1);
    }
    wenc(2);
    {
        dim3 g2(512 / 64, B_ROWS / 128);
        gemm_fp16e<<<g2, 256, FP16E_SMEM>>>(h1h, h1l, weh + off[2], wel + off[2], bv[2],
                                            nullptr, h0h, h0l, B_ROWS, 512, 1024, 1);
    }
    wenc(3);
    {
        dim3 g3(256 / 64, B_ROWS / 128);
        gemm_fp16e<<<g3, 256, FP16E_SMEM>>>(h0h, h0l, weh + off[3], wel + off[3], bv[3],
                                            emb, eh, el, B_ROWS, 256, 512, 0);
    }

    // clustering: S = emb @ centers^T
    vec_split_fp16<<<(K_CENT * D_EMB / 2 + 255) / 256, 256>>>(centers, ch, cl,
                                                              K_CENT * D_EMB / 2);
    {
        dim3 g(K_CENT / 64, B_ROWS / 128);
        gemm_fp16e<<<g, 256, FP16E_SMEM>>>(eh, el, ch, cl, nullptr,
                                           S, nullptr, nullptr, B_ROWS, K_CENT, D_EMB, 0);
    }
    argmin_labels<<<B_ROWS, 256>>>(emb, S, c2, labels);

    // decoder weights (single fp16) + decoder fp16x2
    for (int i = 4; i < 8; i++) {
        dim3 g(fo[i] / 32, fi[i] / 32), b(32, 8);
        wt_single_fp16<<<g, b>>>(W[i], wd + off[i], fi[i], fo[i]);
    }
    {
        dim3 g0(512 / 64, B_ROWS / 128);
        gemm_fp16d<<<g0, 256, FP16D_SMEM>>>(eh, el, wd + off[4], bv[4],
                                            nullptr, h0h, h0l, B_ROWS, 512, 256, 1);
        dim3 g1(1024 / 64, B_ROWS / 128);
        gemm_fp16d<<<g1, 256, FP16D_SMEM>>>(h0h, h0l, wd + off[5], bv[5],
                                            nullptr, h1h, h1l, B_ROWS, 1024, 512, 1);
        dim3 g2(2048 / 64, B_ROWS / 128);
        gemm_fp16d<<<g2, 256, FP16D_SMEM>>>(h1h, h1l, wd + off[6], bv[6],
                                            nullptr, h0h, h0l, B_ROWS, 2048, 1024, 1);
        dim3 g3(1024 / 64, B_ROWS / 128);
        gemm_fp16d<<<g3, 256, FP16D_SMEM>>>(h0h, h0l, wd + off[7], bv[7],
                                            recon, nullptr, nullptr, B_ROWS, 1024, 2048, 0);
    }
}